// round 6
// baseline (speedup 1.0000x reference)
#include <cuda_runtime.h>
#include <cuda_fp16.h>
#include <math.h>
#include <stdint.h>

#define BB 16
#define NN 1024
#define KK 16
#define EE 4
#define D0 128
#define HH 256
#define PP 10
#define EPSF 1.1920928955078125e-07f

#define NCH1 16
#define MTILES 128         // BB*NN/128

// ---------------- device scratch (allocation-free rule) --------------------
__device__ __half g_Af[MTILES*NCH1*128*64];       // A tiled fp16, swizzled
__device__ __half g_Bh0[8*256*64];
__device__ __half g_Bl0[8*256*64];
__device__ __half g_Bh1[16*256*64];
__device__ __half g_Bl1[16*256*64];
__device__ float  g_state[BB*NN*HH];              // fp32 states (final_k)
__device__ __half g_stateh[BB*NN*HH];             // fp16 states (agg fill)
__device__ float  g_pool[BB*8*PP];

// ---------------- PTX helpers ----------------------------------------------
__device__ __forceinline__ uint32_t smem_u32(const void* p){
    uint32_t a; asm("{ .reg .u64 t; cvta.to.shared.u64 t, %1; cvt.u32.u64 %0, t; }" : "=r"(a) : "l"(p));
    return a;
}
#define MBAR_INIT(mb, c)  asm volatile("mbarrier.init.shared.b64 [%0], %1;" :: "r"((uint32_t)(mb)), "r"((uint32_t)(c)) : "memory")
#define MBAR_EXPECT(mb, tx) asm volatile("mbarrier.arrive.expect_tx.shared.b64 _, [%0], %1;" :: "r"((uint32_t)(mb)), "r"((uint32_t)(tx)) : "memory")
#define MBAR_WAIT(mb, ph) do { \
    uint32_t _m = (uint32_t)(mb), _p = (uint32_t)(ph), _d; \
    asm volatile("{\n\t.reg .pred p;\n\tmbarrier.try_wait.parity.acquire.cta.shared::cta.b64 p, [%1], %2;\n\tselp.b32 %0, 1, 0, p;\n\t}" \
        : "=r"(_d) : "r"(_m), "r"(_p) : "memory"); \
    if (!_d) { \
        asm volatile("{\n\t.reg .pred P1;\n\tWL_%=:\n\tmbarrier.try_wait.parity.acquire.cta.shared::cta.b64 P1, [%0], %1, 0x989680;\n\t@P1 bra.uni WD_%=;\n\tbra.uni WL_%=;\n\tWD_%=:\n\t}" \
            :: "r"(_m), "r"(_p) : "memory"); \
    } } while(0)
#define BULK_G2S(dst, src, bytes, mb) \
    asm volatile("cp.async.bulk.shared::cluster.global.mbarrier::complete_tx::bytes [%0], [%1], %2, [%3];" \
        :: "r"((uint32_t)(dst)), "l"(src), "r"((uint32_t)(bytes)), "r"((uint32_t)(mb)) : "memory")

#define LDMX4(r, a) \
    asm volatile("ldmatrix.sync.aligned.m8n8.x4.shared.b16 {%0,%1,%2,%3}, [%4];" \
        : "=r"((r)[0]), "=r"((r)[1]), "=r"((r)[2]), "=r"((r)[3]) : "r"(a))

__device__ __forceinline__ void mma16816(float* c, const uint32_t* a, uint32_t b0, uint32_t b1){
    asm volatile("mma.sync.aligned.m16n8k16.row.col.f32.f16.f16.f32 "
        "{%0,%1,%2,%3}, {%4,%5,%6,%7}, {%8,%9}, {%0,%1,%2,%3};"
        : "+f"(c[0]), "+f"(c[1]), "+f"(c[2]), "+f"(c[3])
        : "r"(a[0]), "r"(a[1]), "r"(a[2]), "r"(a[3]), "r"(b0), "r"(b1));
}

__device__ __forceinline__ uint32_t tswz(int row, int g){
    return (uint32_t)(row*128 + (((g ^ (row & 7))) << 4));
}

// ---------------------------------------------------------------------------
// 1) Aggregation, fp16x2 path. SMEM slice: half[1024][64].
//    Per (node, k): 1 uniform LDG.128 of 4 indices; per (node, e, k):
//    1 LDS.32 (half2 = 2 cols) + 1 HADD2. Two chains (k even/odd) per e.
// ---------------------------------------------------------------------------
__global__ __launch_bounds__(512) void agg_k(const __half* __restrict__ Sh,
        const int* __restrict__ nf, const float* __restrict__ emb,
        const int* __restrict__ nn_idx, const float* __restrict__ mask,
        int D, int nch, int useEmb, int nsplit_shift){
    extern __shared__ __half sbuf[];                // [1024][64]
    int b   = blockIdx.x;
    int d0c = blockIdx.y * 64;
    int tid = threadIdx.x, lane = tid & 31, w = tid >> 5;

    if (useEmb){
        const int* nfb = nf + b*NN;
        for (int i = tid; i < NN*32; i += 512){
            int row = i >> 5, cp = (i & 31) << 1;
            const float* ep = emb + (size_t)nfb[row]*D0 + d0c + cp;
            float2 v = make_float2(ep[0], ep[1]);
            *(__half2*)&sbuf[row*64 + cp] = __floats2half2_rn(v.x, v.y);
        }
    } else {
        const __half* Sb = Sh + (size_t)b*NN*HH;
        for (int i = tid; i < NN*16; i += 512){
            int row = i >> 4, cp = (i & 15) << 2;
            *(uint2*)&sbuf[row*64 + cp] = *(const uint2*)&Sb[(size_t)row*HH + d0c + cp];
        }
    }
    __syncthreads();

    int nPer  = NN >> nsplit_shift;
    int nbase = blockIdx.z * nPer;
    char* Ag = (char*)g_Af;
    const __half2* sb2 = (const __half2*)sbuf;

    for (int n = nbase + w; n < nbase + nPer; n += 16){
        const int4* ip4 = (const int4*)(nn_idx + ((size_t)(b*NN + n))*(KK*EE));
        __half2 sA[4], sB[4];
        #pragma unroll
        for (int e = 0; e < 4; e++){ sA[e] = __float2half2_rn(0.f); sB[e] = sA[e]; }
        #pragma unroll
        for (int g = 0; g < KK; g += 2){
            int4 q0 = __ldg(&ip4[g]);
            int4 q1 = __ldg(&ip4[g+1]);
            sA[0] = __hadd2(sA[0], sb2[q0.x*32 + lane]);
            sA[1] = __hadd2(sA[1], sb2[q0.y*32 + lane]);
            sA[2] = __hadd2(sA[2], sb2[q0.z*32 + lane]);
            sA[3] = __hadd2(sA[3], sb2[q0.w*32 + lane]);
            sB[0] = __hadd2(sB[0], sb2[q1.x*32 + lane]);
            sB[1] = __hadd2(sB[1], sb2[q1.y*32 + lane]);
            sB[2] = __hadd2(sB[2], sb2[q1.z*32 + lane]);
            sB[3] = __hadd2(sB[3], sb2[q1.w*32 + lane]);
        }
        __half2 m2 = __float2half2_rn(mask[b*NN + n] * 0.0625f);   // exact pow2 scale
        int mtile = b*8 + (n >> 7);
        int mrow  = n & 127;
        size_t tbase = ((size_t)mtile*nch) << 14;
        uint32_t inrow = (((uint32_t)((lane >> 2) ^ (mrow & 7))) << 4) + (lane & 3)*4;
        #pragma unroll
        for (int e = 0; e < EE; e++){
            __half2 r = __hmul2(__hadd2(sA[e], sB[e]), m2);
            int ch = (e*D + d0c) >> 6;                      // kin = 2*lane
            *(__half2*)(Ag + tbase + (((size_t)ch*128 + mrow) << 7) + inrow) = r;
        }
    }
}

// ---------------------------------------------------------------------------
// 2) Weight convert (both layers, one launch)
// ---------------------------------------------------------------------------
__global__ void convw_k(const float* __restrict__ W0, const float* __restrict__ W1){
    int t = blockIdx.x*256 + threadIdx.x;           // 0 .. 49151
    const float* W; __half *Bh, *Bl; int g;
    if (t < 16384){ W = W0; Bh = g_Bh0; Bl = g_Bl0; g = t; }
    else          { W = W1; Bh = g_Bh1; Bl = g_Bl1; g = t - 16384; }
    int n  = g & 255;
    int kq = g >> 8;
    __half hv[8], lv[8];
    #pragma unroll
    for (int j = 0; j < 8; j++){
        float v = W[(size_t)(kq*8 + j)*HH + n];
        __half h = __float2half(v);
        hv[j] = h;
        lv[j] = __float2half(v - __half2float(h));
    }
    int ch = kq >> 3;
    size_t byt = (((size_t)(ch*256 + n)) << 7) + ((((kq & 7) ^ (n & 7))) << 4);
    *(uint4*)((char*)Bh + byt) = *(uint4*)hv;
    *(uint4*)((char*)Bl + byt) = *(uint4*)lv;
}

// ---------------------------------------------------------------------------
// 3) GEMM: 2-pass compensated fp16, cp.async.bulk staging, fused
//    bias+ReLU+L2-norm epilogue; writes fp32 + fp16 state.
// ---------------------------------------------------------------------------
#define STG 81920
#define GEMM_SMEM (2*STG + 64)
#define EPI_STR 258

__global__ __launch_bounds__(512, 1) void gemm2_k(
        const __half* __restrict__ Agl, const __half* __restrict__ Bhg,
        const __half* __restrict__ Blg, int nch,
        const float* __restrict__ bias, float* __restrict__ S){
    extern __shared__ char smx[];
    uint32_t sb0 = smem_u32(smx);
    uint32_t mb  = sb0 + 2*STG;
    int tid = threadIdx.x, lane = tid & 31, w = tid >> 5;
    int wm = w >> 3, wn = w & 7;
    int mtile = blockIdx.x;

    if (tid == 0){ MBAR_INIT(mb, 1); MBAR_INIT(mb + 8, 1); }
    __syncthreads();

    float c[4][4][4];
    #pragma unroll
    for (int mi = 0; mi < 4; mi++)
        #pragma unroll
        for (int nj = 0; nj < 4; nj++)
            #pragma unroll
            for (int q = 0; q < 4; q++) c[mi][nj][q] = 0.f;

    auto issue = [&](int ch){
        int st = ch & 1;
        uint32_t d = sb0 + st*STG;
        uint32_t m = mb + st*8;
        MBAR_EXPECT(m, STG);
        BULK_G2S(d,         (const char*)Agl + (((size_t)(mtile*nch + ch)) << 14), 16384, m);
        BULK_G2S(d + 16384, (const char*)Bhg + (((size_t)ch) << 15),               32768, m);
        BULK_G2S(d + 49152, (const char*)Blg + (((size_t)ch) << 15),               32768, m);
    };

    if (tid == 0){ issue(0); issue(1); }
    int ph0 = 0, ph1 = 0;

    for (int ch = 0; ch < nch; ch++){
        int st = ch & 1;
        if (st == 0){ MBAR_WAIT(mb,     ph0); ph0 ^= 1; }
        else        { MBAR_WAIT(mb + 8, ph1); ph1 ^= 1; }

        uint32_t ab = sb0 + st*STG;
        uint32_t bh = ab + 16384;
        uint32_t bl = ab + 49152;
        #pragma unroll
        for (int s = 0; s < 4; s++){
            int lrow = lane & 15;
            int g = 2*s + (lane >> 4);
            uint32_t a[4][4], bq[2][4], bp[2][4];
            #pragma unroll
            for (int mi = 0; mi < 4; mi++){
                int row = wm*64 + mi*16 + lrow;
                LDMX4(a[mi], ab + tswz(row, g));
            }
            #pragma unroll
            for (int nj = 0; nj < 2; nj++){
                int row = wn*32 + nj*16 + lrow;
                LDMX4(bq[nj], bh + tswz(row, g));
                LDMX4(bp[nj], bl + tswz(row, g));
            }
            #pragma unroll
            for (int mi = 0; mi < 4; mi++)
                #pragma unroll
                for (int nj = 0; nj < 2; nj++){
                    mma16816(c[mi][2*nj+0], a[mi], bq[nj][0], bq[nj][2]);
                    mma16816(c[mi][2*nj+1], a[mi], bq[nj][1], bq[nj][3]);
                    mma16816(c[mi][2*nj+0], a[mi], bp[nj][0], bp[nj][2]);
                    mma16816(c[mi][2*nj+1], a[mi], bp[nj][1], bp[nj][3]);
                }
        }
        __syncthreads();
        if (tid == 0 && ch + 2 < nch) issue(ch + 2);
    }
    __syncthreads();

    // --- epilogue: bias + relu into smem, fused row L2-norm ---
    float* sbuf = (float*)smx;
    int qr = lane >> 2, qc = (lane & 3)*2;
    #pragma unroll
    for (int mi = 0; mi < 4; mi++){
        int r0 = wm*64 + mi*16 + qr;
        #pragma unroll
        for (int nj = 0; nj < 4; nj++){
            int col = wn*32 + nj*8 + qc;
            float b0 = bias[col], b1 = bias[col+1];
            *(float2*)&sbuf[(size_t)r0*EPI_STR + col] =
                make_float2(fmaxf(c[mi][nj][0] + b0, 0.f), fmaxf(c[mi][nj][1] + b1, 0.f));
            *(float2*)&sbuf[(size_t)(r0+8)*EPI_STR + col] =
                make_float2(fmaxf(c[mi][nj][2] + b0, 0.f), fmaxf(c[mi][nj][3] + b1, 0.f));
        }
    }
    __syncthreads();

    int m0 = mtile*128;
    #pragma unroll
    for (int r = 0; r < 8; r++){
        int row = w*8 + r;
        const float2* rp2 = (const float2*)&sbuf[(size_t)row*EPI_STR];
        float2 v2[4]; float ss = 0.f;
        #pragma unroll
        for (int j = 0; j < 4; j++){
            v2[j] = rp2[lane + 32*j];
            ss += v2[j].x*v2[j].x + v2[j].y*v2[j].y;
        }
        #pragma unroll
        for (int off = 16; off; off >>= 1) ss += __shfl_xor_sync(0xffffffffu, ss, off);
        float inv = 1.0f/(sqrtf(ss) + EPSF);
        float2*  op  = (float2*)(S + (size_t)(m0 + row)*HH);
        __half2* oph = (__half2*)(g_stateh + (size_t)(m0 + row)*HH);
        #pragma unroll
        for (int j = 0; j < 4; j++){
            float x = v2[j].x*inv, y = v2[j].y*inv;
            op[lane + 32*j]  = make_float2(x, y);
            oph[lane + 32*j] = __floats2half2_rn(x, y);
        }
    }
}

// ---------------------------------------------------------------------------
// 4) Output head + pooling
// ---------------------------------------------------------------------------
__global__ void final_k(const float* __restrict__ S,
                        const float* __restrict__ Wout, const float* __restrict__ bout,
                        const float* __restrict__ Watt, const float* __restrict__ batt){
    __shared__ float wt[PP*HH];
    __shared__ float wa[HH];
    __shared__ float red[8][PP];
    int b = blockIdx.x, seg = blockIdx.y;
    int tid = threadIdx.x, lane = tid & 31, w = tid >> 5;

    for (int i = tid; i < PP*HH; i += 256){
        int d = i / PP, p = i - d*PP;
        wt[p*HH + d] = Wout[i];
    }
    if (tid < HH) wa[tid] = Watt[tid];
    __syncthreads();

    float accp = 0.f;
    float ba = batt[0];
    for (int t = 0; t < 16; t++){
        int n = seg*128 + w*16 + t;
        const float* sp = S + (size_t)(b*NN + n)*HH;
        float s[8], att = 0.f, y[PP];
        #pragma unroll
        for (int p = 0; p < PP; p++) y[p] = 0.f;
        #pragma unroll
        for (int j = 0; j < 8; j++){
            s[j] = sp[lane + 32*j];
            att += s[j]*wa[lane + 32*j];
        }
        #pragma unroll
        for (int p = 0; p < PP; p++)
            #pragma unroll
            for (int j = 0; j < 8; j++) y[p] += s[j]*wt[p*HH + lane + 32*j];
        #pragma unroll
        for (int off = 16; off; off >>= 1){
            att += __shfl_xor_sync(0xffffffffu, att, off);
            #pragma unroll
            for (int p = 0; p < PP; p++) y[p] += __shfl_xor_sync(0xffffffffu, y[p], off);
        }
        float a = 1.0f/(1.0f + expf(-(att + ba)));
        if (lane < PP) accp += a * (y[lane] + bout[lane]);
    }
    if (lane < PP) red[w][lane] = accp;
    __syncthreads();
    if (tid < PP){
        float sum = 0.f;
        #pragma unroll
        for (int w2 = 0; w2 < 8; w2++) sum += red[w2][tid];
        g_pool[(b*8 + seg)*PP + tid] = sum;
    }
}

__global__ void reduce_k(float* __restrict__ out){
    int i = threadIdx.x;
    if (i < BB*PP){
        int b = i / PP, p = i - b*PP;
        float s = 0.f;
        #pragma unroll
        for (int seg = 0; seg < 8; seg++) s += g_pool[(b*8 + seg)*PP + p];
        out[i] = s * (1.0f/NN);
    }
}

// ---------------------------------------------------------------------------
extern "C" void kernel_launch(void* const* d_in, const int* in_sizes, int n_in,
                              void* d_out, int out_size){
    (void)in_sizes; (void)n_in; (void)out_size;
    const int*   nf   = (const int*)  d_in[0];
    const int*   nn   = (const int*)  d_in[1];
    const float* mask = (const float*)d_in[2];
    const float* emb  = (const float*)d_in[3];
    const float* W0   = (const float*)d_in[4];
    const float* b0   = (const float*)d_in[5];
    const float* W1   = (const float*)d_in[6];
    const float* b1   = (const float*)d_in[7];
    const float* Wout = (const float*)d_in[8];
    const float* bout = (const float*)d_in[9];
    const float* Watt = (const float*)d_in[10];
    const float* batt = (const float*)d_in[11];
    float* out = (float*)d_out;

    float *state; __half *stateh, *af, *bh0, *bl0, *bh1, *bl1;
    cudaGetSymbolAddress((void**)&state,  g_state);
    cudaGetSymbolAddress((void**)&stateh, g_stateh);
    cudaGetSymbolAddress((void**)&af,  g_Af);
    cudaGetSymbolAddress((void**)&bh0, g_Bh0);
    cudaGetSymbolAddress((void**)&bl0, g_Bl0);
    cudaGetSymbolAddress((void**)&bh1, g_Bh1);
    cudaGetSymbolAddress((void**)&bl1, g_Bl1);

    cudaFuncSetAttribute(agg_k,   cudaFuncAttributeMaxDynamicSharedMemorySize, 131072);
    cudaFuncSetAttribute(gemm2_k, cudaFuncAttributeMaxDynamicSharedMemorySize, GEMM_SMEM);

    convw_k<<<192, 256>>>(W0, W1);

    // Layer 0 (Kd=512, nch=8): embed fused, 64-col slices, z-split 4
    agg_k<<<dim3(BB, D0/64, 4), 512, 131072>>>(stateh, nf, emb, nn, mask, D0, 8, 1, 2);
    gemm2_k<<<MTILES, 512, GEMM_SMEM>>>(af, bh0, bl0, 8, b0, state);

    // Layer 1 (Kd=1024, nch=16): fp16 state fill, z-split 2
    agg_k<<<dim3(BB, HH/64, 2), 512, 131072>>>(stateh, nf, emb, nn, mask, HH, 16, 0, 1);
    gemm2_k<<<MTILES, 512, GEMM_SMEM>>>(af, bh1, bl1, 16, b1, state);

    final_k<<<dim3(BB, 8), 256>>>(state, Wout, bout, Watt, batt);
    reduce_k<<<1, 192>>>(out);
}

// round 7
// speedup vs baseline: 1.6705x; 1.6705x over previous
#include <cuda_runtime.h>
#include <cuda_fp16.h>
#include <math.h>
#include <stdint.h>

#define BB 16
#define NN 1024
#define KK 16
#define EE 4
#define D0 128
#define HH 256
#define PP 10
#define EPSF 1.1920928955078125e-07f

#define NCH1 16
#define MTILES 128         // BB*NN/128

// ---------------- device scratch (allocation-free rule) --------------------
__device__ __half g_Af[MTILES*NCH1*128*64];       // A tiled fp16, swizzled
__device__ __half g_Bh0[8*256*64];
__device__ __half g_Bl0[8*256*64];
__device__ __half g_Bh1[16*256*64];
__device__ __half g_Bl1[16*256*64];
__device__ float  g_state[BB*NN*HH];              // fp32 states (final_k)
__device__ __half g_stateh[BB*NN*HH];             // fp16 states (agg fill)
__device__ float  g_pool[BB*8*PP];

// ---------------- PTX helpers ----------------------------------------------
__device__ __forceinline__ uint32_t smem_u32(const void* p){
    uint32_t a; asm("{ .reg .u64 t; cvta.to.shared.u64 t, %1; cvt.u32.u64 %0, t; }" : "=r"(a) : "l"(p));
    return a;
}
#define MBAR_INIT(mb, c)  asm volatile("mbarrier.init.shared.b64 [%0], %1;" :: "r"((uint32_t)(mb)), "r"((uint32_t)(c)) : "memory")
#define MBAR_EXPECT(mb, tx) asm volatile("mbarrier.arrive.expect_tx.shared.b64 _, [%0], %1;" :: "r"((uint32_t)(mb)), "r"((uint32_t)(tx)) : "memory")
#define MBAR_WAIT(mb, ph) do { \
    uint32_t _m = (uint32_t)(mb), _p = (uint32_t)(ph), _d; \
    asm volatile("{\n\t.reg .pred p;\n\tmbarrier.try_wait.parity.acquire.cta.shared::cta.b64 p, [%1], %2;\n\tselp.b32 %0, 1, 0, p;\n\t}" \
        : "=r"(_d) : "r"(_m), "r"(_p) : "memory"); \
    if (!_d) { \
        asm volatile("{\n\t.reg .pred P1;\n\tWL_%=:\n\tmbarrier.try_wait.parity.acquire.cta.shared::cta.b64 P1, [%0], %1, 0x989680;\n\t@P1 bra.uni WD_%=;\n\tbra.uni WL_%=;\n\tWD_%=:\n\t}" \
            :: "r"(_m), "r"(_p) : "memory"); \
    } } while(0)
#define BULK_G2S(dst, src, bytes, mb) \
    asm volatile("cp.async.bulk.shared::cluster.global.mbarrier::complete_tx::bytes [%0], [%1], %2, [%3];" \
        :: "r"((uint32_t)(dst)), "l"(src), "r"((uint32_t)(bytes)), "r"((uint32_t)(mb)) : "memory")

#define LDMX4(r, a) \
    asm volatile("ldmatrix.sync.aligned.m8n8.x4.shared.b16 {%0,%1,%2,%3}, [%4];" \
        : "=r"((r)[0]), "=r"((r)[1]), "=r"((r)[2]), "=r"((r)[3]) : "r"(a))

__device__ __forceinline__ void mma16816(float* c, const uint32_t* a, uint32_t b0, uint32_t b1){
    asm volatile("mma.sync.aligned.m16n8k16.row.col.f32.f16.f16.f32 "
        "{%0,%1,%2,%3}, {%4,%5,%6,%7}, {%8,%9}, {%0,%1,%2,%3};"
        : "+f"(c[0]), "+f"(c[1]), "+f"(c[2]), "+f"(c[3])
        : "r"(a[0]), "r"(a[1]), "r"(a[2]), "r"(a[3]), "r"(b0), "r"(b1));
}

__device__ __forceinline__ uint32_t tswz(int row, int g){
    return (uint32_t)(row*128 + (((g ^ (row & 7))) << 4));
}

// ---------------------------------------------------------------------------
// 1) Aggregation, fp16x2 path, 1024 threads (32 warps -> 50% occ for latency
//    hiding). SMEM slice: half[1024][64]. Per (node, e, k): 1 LDS.32 + 1 HADD2.
// ---------------------------------------------------------------------------
__global__ __launch_bounds__(1024) void agg_k(const __half* __restrict__ Sh,
        const int* __restrict__ nf, const float* __restrict__ emb,
        const int* __restrict__ nn_idx, const float* __restrict__ mask,
        int D, int nch, int useEmb, int nsplit_shift){
    extern __shared__ __half sbuf[];                // [1024][64]
    int b   = blockIdx.x;
    int d0c = blockIdx.y * 64;
    int tid = threadIdx.x, lane = tid & 31, w = tid >> 5;

    if (useEmb){
        const int* nfb = nf + b*NN;
        for (int i = tid; i < NN*32; i += 1024){
            int row = i >> 5, cp = (i & 31) << 1;
            const float* ep = emb + (size_t)nfb[row]*D0 + d0c + cp;
            float2 v = make_float2(ep[0], ep[1]);
            *(__half2*)&sbuf[row*64 + cp] = __floats2half2_rn(v.x, v.y);
        }
    } else {
        const __half* Sb = Sh + (size_t)b*NN*HH;
        for (int i = tid; i < NN*16; i += 1024){
            int row = i >> 4, cp = (i & 15) << 2;
            *(uint2*)&sbuf[row*64 + cp] = *(const uint2*)&Sb[(size_t)row*HH + d0c + cp];
        }
    }
    __syncthreads();

    int nPer  = NN >> nsplit_shift;
    int nbase = blockIdx.z * nPer;
    char* Ag = (char*)g_Af;
    const __half2* sb2 = (const __half2*)sbuf;

    for (int n = nbase + w; n < nbase + nPer; n += 32){
        const int4* ip4 = (const int4*)(nn_idx + ((size_t)(b*NN + n))*(KK*EE));
        __half2 sA[4], sB[4];
        #pragma unroll
        for (int e = 0; e < 4; e++){ sA[e] = __float2half2_rn(0.f); sB[e] = sA[e]; }
        #pragma unroll
        for (int g = 0; g < KK; g += 2){
            int4 q0 = __ldg(&ip4[g]);
            int4 q1 = __ldg(&ip4[g+1]);
            sA[0] = __hadd2(sA[0], sb2[q0.x*32 + lane]);
            sA[1] = __hadd2(sA[1], sb2[q0.y*32 + lane]);
            sA[2] = __hadd2(sA[2], sb2[q0.z*32 + lane]);
            sA[3] = __hadd2(sA[3], sb2[q0.w*32 + lane]);
            sB[0] = __hadd2(sB[0], sb2[q1.x*32 + lane]);
            sB[1] = __hadd2(sB[1], sb2[q1.y*32 + lane]);
            sB[2] = __hadd2(sB[2], sb2[q1.z*32 + lane]);
            sB[3] = __hadd2(sB[3], sb2[q1.w*32 + lane]);
        }
        __half2 m2 = __float2half2_rn(mask[b*NN + n] * 0.0625f);   // exact pow2 scale
        int mtile = b*8 + (n >> 7);
        int mrow  = n & 127;
        size_t tbase = ((size_t)mtile*nch) << 14;
        uint32_t inrow = (((uint32_t)((lane >> 2) ^ (mrow & 7))) << 4) + (lane & 3)*4;
        #pragma unroll
        for (int e = 0; e < EE; e++){
            __half2 r = __hmul2(__hadd2(sA[e], sB[e]), m2);
            int ch = (e*D + d0c) >> 6;                      // kin = 2*lane
            *(__half2*)(Ag + tbase + (((size_t)ch*128 + mrow) << 7) + inrow) = r;
        }
    }
}

// ---------------------------------------------------------------------------
// 2) Weight convert (both layers, one launch)
// ---------------------------------------------------------------------------
__global__ void convw_k(const float* __restrict__ W0, const float* __restrict__ W1){
    int t = blockIdx.x*256 + threadIdx.x;           // 0 .. 49151
    const float* W; __half *Bh, *Bl; int g;
    if (t < 16384){ W = W0; Bh = g_Bh0; Bl = g_Bl0; g = t; }
    else          { W = W1; Bh = g_Bh1; Bl = g_Bl1; g = t - 16384; }
    int n  = g & 255;
    int kq = g >> 8;
    __half hv[8], lv[8];
    #pragma unroll
    for (int j = 0; j < 8; j++){
        float v = W[(size_t)(kq*8 + j)*HH + n];
        __half h = __float2half(v);
        hv[j] = h;
        lv[j] = __float2half(v - __half2float(h));
    }
    int ch = kq >> 3;
    size_t byt = (((size_t)(ch*256 + n)) << 7) + ((((kq & 7) ^ (n & 7))) << 4);
    *(uint4*)((char*)Bh + byt) = *(uint4*)hv;
    *(uint4*)((char*)Bl + byt) = *(uint4*)lv;
}

// ---------------------------------------------------------------------------
// 3) GEMM: 2-pass compensated fp16, cp.async.bulk staging, fused
//    bias+ReLU+L2-norm epilogue; writes fp32 + fp16 state.
// ---------------------------------------------------------------------------
#define STG 81920
#define GEMM_SMEM (2*STG + 64)
#define EPI_STR 258

__global__ __launch_bounds__(512, 1) void gemm2_k(
        const __half* __restrict__ Agl, const __half* __restrict__ Bhg,
        const __half* __restrict__ Blg, int nch,
        const float* __restrict__ bias, float* __restrict__ S){
    extern __shared__ char smx[];
    uint32_t sb0 = smem_u32(smx);
    uint32_t mb  = sb0 + 2*STG;
    int tid = threadIdx.x, lane = tid & 31, w = tid >> 5;
    int wm = w >> 3, wn = w & 7;
    int mtile = blockIdx.x;

    if (tid == 0){ MBAR_INIT(mb, 1); MBAR_INIT(mb + 8, 1); }
    __syncthreads();

    float c[4][4][4];
    #pragma unroll
    for (int mi = 0; mi < 4; mi++)
        #pragma unroll
        for (int nj = 0; nj < 4; nj++)
            #pragma unroll
            for (int q = 0; q < 4; q++) c[mi][nj][q] = 0.f;

    auto issue = [&](int ch){
        int st = ch & 1;
        uint32_t d = sb0 + st*STG;
        uint32_t m = mb + st*8;
        MBAR_EXPECT(m, STG);
        BULK_G2S(d,         (const char*)Agl + (((size_t)(mtile*nch + ch)) << 14), 16384, m);
        BULK_G2S(d + 16384, (const char*)Bhg + (((size_t)ch) << 15),               32768, m);
        BULK_G2S(d + 49152, (const char*)Blg + (((size_t)ch) << 15),               32768, m);
    };

    if (tid == 0){ issue(0); issue(1); }
    int ph0 = 0, ph1 = 0;

    for (int ch = 0; ch < nch; ch++){
        int st = ch & 1;
        if (st == 0){ MBAR_WAIT(mb,     ph0); ph0 ^= 1; }
        else        { MBAR_WAIT(mb + 8, ph1); ph1 ^= 1; }

        uint32_t ab = sb0 + st*STG;
        uint32_t bh = ab + 16384;
        uint32_t bl = ab + 49152;
        #pragma unroll
        for (int s = 0; s < 4; s++){
            int lrow = lane & 15;
            int g = 2*s + (lane >> 4);
            uint32_t a[4][4], bq[2][4], bp[2][4];
            #pragma unroll
            for (int mi = 0; mi < 4; mi++){
                int row = wm*64 + mi*16 + lrow;
                LDMX4(a[mi], ab + tswz(row, g));
            }
            #pragma unroll
            for (int nj = 0; nj < 2; nj++){
                int row = wn*32 + nj*16 + lrow;
                LDMX4(bq[nj], bh + tswz(row, g));
                LDMX4(bp[nj], bl + tswz(row, g));
            }
            #pragma unroll
            for (int mi = 0; mi < 4; mi++)
                #pragma unroll
                for (int nj = 0; nj < 2; nj++){
                    mma16816(c[mi][2*nj+0], a[mi], bq[nj][0], bq[nj][2]);
                    mma16816(c[mi][2*nj+1], a[mi], bq[nj][1], bq[nj][3]);
                    mma16816(c[mi][2*nj+0], a[mi], bp[nj][0], bp[nj][2]);
                    mma16816(c[mi][2*nj+1], a[mi], bp[nj][1], bp[nj][3]);
                }
        }
        __syncthreads();
        if (tid == 0 && ch + 2 < nch) issue(ch + 2);
    }
    __syncthreads();

    // --- epilogue: bias + relu into smem, fused row L2-norm ---
    float* sbuf = (float*)smx;
    int qr = lane >> 2, qc = (lane & 3)*2;
    #pragma unroll
    for (int mi = 0; mi < 4; mi++){
        int r0 = wm*64 + mi*16 + qr;
        #pragma unroll
        for (int nj = 0; nj < 4; nj++){
            int col = wn*32 + nj*8 + qc;
            float b0 = bias[col], b1 = bias[col+1];
            *(float2*)&sbuf[(size_t)r0*EPI_STR + col] =
                make_float2(fmaxf(c[mi][nj][0] + b0, 0.f), fmaxf(c[mi][nj][1] + b1, 0.f));
            *(float2*)&sbuf[(size_t)(r0+8)*EPI_STR + col] =
                make_float2(fmaxf(c[mi][nj][2] + b0, 0.f), fmaxf(c[mi][nj][3] + b1, 0.f));
        }
    }
    __syncthreads();

    int m0 = mtile*128;
    #pragma unroll
    for (int r = 0; r < 8; r++){
        int row = w*8 + r;
        const float2* rp2 = (const float2*)&sbuf[(size_t)row*EPI_STR];
        float2 v2[4]; float ss = 0.f;
        #pragma unroll
        for (int j = 0; j < 4; j++){
            v2[j] = rp2[lane + 32*j];
            ss += v2[j].x*v2[j].x + v2[j].y*v2[j].y;
        }
        #pragma unroll
        for (int off = 16; off; off >>= 1) ss += __shfl_xor_sync(0xffffffffu, ss, off);
        float inv = 1.0f/(sqrtf(ss) + EPSF);
        float2*  op  = (float2*)(S + (size_t)(m0 + row)*HH);
        __half2* oph = (__half2*)(g_stateh + (size_t)(m0 + row)*HH);
        #pragma unroll
        for (int j = 0; j < 4; j++){
            float x = v2[j].x*inv, y = v2[j].y*inv;
            op[lane + 32*j]  = make_float2(x, y);
            oph[lane + 32*j] = __floats2half2_rn(x, y);
        }
    }
}

// ---------------------------------------------------------------------------
// 4) Output head + pooling
// ---------------------------------------------------------------------------
__global__ void final_k(const float* __restrict__ S,
                        const float* __restrict__ Wout, const float* __restrict__ bout,
                        const float* __restrict__ Watt, const float* __restrict__ batt){
    __shared__ float wt[PP*HH];
    __shared__ float wa[HH];
    __shared__ float red[8][PP];
    int b = blockIdx.x, seg = blockIdx.y;
    int tid = threadIdx.x, lane = tid & 31, w = tid >> 5;

    for (int i = tid; i < PP*HH; i += 256){
        int d = i / PP, p = i - d*PP;
        wt[p*HH + d] = Wout[i];
    }
    if (tid < HH) wa[tid] = Watt[tid];
    __syncthreads();

    float accp = 0.f;
    float ba = batt[0];
    for (int t = 0; t < 16; t++){
        int n = seg*128 + w*16 + t;
        const float* sp = S + (size_t)(b*NN + n)*HH;
        float s[8], att = 0.f, y[PP];
        #pragma unroll
        for (int p = 0; p < PP; p++) y[p] = 0.f;
        #pragma unroll
        for (int j = 0; j < 8; j++){
            s[j] = sp[lane + 32*j];
            att += s[j]*wa[lane + 32*j];
        }
        #pragma unroll
        for (int p = 0; p < PP; p++)
            #pragma unroll
            for (int j = 0; j < 8; j++) y[p] += s[j]*wt[p*HH + lane + 32*j];
        #pragma unroll
        for (int off = 16; off; off >>= 1){
            att += __shfl_xor_sync(0xffffffffu, att, off);
            #pragma unroll
            for (int p = 0; p < PP; p++) y[p] += __shfl_xor_sync(0xffffffffu, y[p], off);
        }
        float a = 1.0f/(1.0f + expf(-(att + ba)));
        if (lane < PP) accp += a * (y[lane] + bout[lane]);
    }
    if (lane < PP) red[w][lane] = accp;
    __syncthreads();
    if (tid < PP){
        float sum = 0.f;
        #pragma unroll
        for (int w2 = 0; w2 < 8; w2++) sum += red[w2][tid];
        g_pool[(b*8 + seg)*PP + tid] = sum;
    }
}

__global__ void reduce_k(float* __restrict__ out){
    int i = threadIdx.x;
    if (i < BB*PP){
        int b = i / PP, p = i - b*PP;
        float s = 0.f;
        #pragma unroll
        for (int seg = 0; seg < 8; seg++) s += g_pool[(b*8 + seg)*PP + p];
        out[i] = s * (1.0f/NN);
    }
}

// ---------------------------------------------------------------------------
extern "C" void kernel_launch(void* const* d_in, const int* in_sizes, int n_in,
                              void* d_out, int out_size){
    (void)in_sizes; (void)n_in; (void)out_size;
    const int*   nf   = (const int*)  d_in[0];
    const int*   nn   = (const int*)  d_in[1];
    const float* mask = (const float*)d_in[2];
    const float* emb  = (const float*)d_in[3];
    const float* W0   = (const float*)d_in[4];
    const float* b0   = (const float*)d_in[5];
    const float* W1   = (const float*)d_in[6];
    const float* b1   = (const float*)d_in[7];
    const float* Wout = (const float*)d_in[8];
    const float* bout = (const float*)d_in[9];
    const float* Watt = (const float*)d_in[10];
    const float* batt = (const float*)d_in[11];
    float* out = (float*)d_out;

    float *state; __half *stateh, *af, *bh0, *bl0, *bh1, *bl1;
    cudaGetSymbolAddress((void**)&state,  g_state);
    cudaGetSymbolAddress((void**)&stateh, g_stateh);
    cudaGetSymbolAddress((void**)&af,  g_Af);
    cudaGetSymbolAddress((void**)&bh0, g_Bh0);
    cudaGetSymbolAddress((void**)&bl0, g_Bl0);
    cudaGetSymbolAddress((void**)&bh1, g_Bh1);
    cudaGetSymbolAddress((void**)&bl1, g_Bl1);

    cudaFuncSetAttribute(agg_k,   cudaFuncAttributeMaxDynamicSharedMemorySize, 131072);
    cudaFuncSetAttribute(gemm2_k, cudaFuncAttributeMaxDynamicSharedMemorySize, GEMM_SMEM);

    convw_k<<<192, 256>>>(W0, W1);

    // Layer 0 (Kd=512, nch=8): embed fused, 64-col slices, z-split 4, 32 warps
    agg_k<<<dim3(BB, D0/64, 4), 1024, 131072>>>(stateh, nf, emb, nn, mask, D0, 8, 1, 2);
    gemm2_k<<<MTILES, 512, GEMM_SMEM>>>(af, bh0, bl0, 8, b0, state);

    // Layer 1 (Kd=1024, nch=16): fp16 state fill, z-split 2, 32 warps
    agg_k<<<dim3(BB, HH/64, 2), 1024, 131072>>>(stateh, nf, emb, nn, mask, HH, 16, 0, 1);
    gemm2_k<<<MTILES, 512, GEMM_SMEM>>>(af, bh1, bl1, 16, b1, state);

    final_k<<<dim3(BB, 8), 256>>>(state, Wout, bout, Watt, batt);
    reduce_k<<<1, 192>>>(out);
}

// round 8
// speedup vs baseline: 1.8910x; 1.1320x over previous
#include <cuda_runtime.h>
#include <cuda_fp16.h>
#include <math.h>
#include <stdint.h>

#define BB 16
#define NN 1024
#define KK 16
#define EE 4
#define D0 128
#define HH 256
#define PP 10
#define EPSF 1.1920928955078125e-07f

#define NCH1 16
#define MTILES 128         // BB*NN/128

// ---------------- device scratch (allocation-free rule) --------------------
__device__ __half g_Af[MTILES*NCH1*128*64];       // A tiled fp16, swizzled
__device__ __half g_Bh0[8*256*64];
__device__ __half g_Bl0[8*256*64];
__device__ __half g_Bh1[16*256*64];
__device__ __half g_Bl1[16*256*64];
__device__ float  g_state[BB*NN*HH];              // fp32 states (final_k)
__device__ __half g_stateh[BB*NN*HH];             // fp16 states (agg fill)
__device__ float  g_pool[BB*8*PP];

// ---------------- PTX helpers ----------------------------------------------
__device__ __forceinline__ uint32_t smem_u32(const void* p){
    uint32_t a; asm("{ .reg .u64 t; cvta.to.shared.u64 t, %1; cvt.u32.u64 %0, t; }" : "=r"(a) : "l"(p));
    return a;
}
#define MBAR_INIT(mb, c)  asm volatile("mbarrier.init.shared.b64 [%0], %1;" :: "r"((uint32_t)(mb)), "r"((uint32_t)(c)) : "memory")
#define MBAR_EXPECT(mb, tx) asm volatile("mbarrier.arrive.expect_tx.shared.b64 _, [%0], %1;" :: "r"((uint32_t)(mb)), "r"((uint32_t)(tx)) : "memory")
#define MBAR_WAIT(mb, ph) do { \
    uint32_t _m = (uint32_t)(mb), _p = (uint32_t)(ph), _d; \
    asm volatile("{\n\t.reg .pred p;\n\tmbarrier.try_wait.parity.acquire.cta.shared::cta.b64 p, [%1], %2;\n\tselp.b32 %0, 1, 0, p;\n\t}" \
        : "=r"(_d) : "r"(_m), "r"(_p) : "memory"); \
    if (!_d) { \
        asm volatile("{\n\t.reg .pred P1;\n\tWL_%=:\n\tmbarrier.try_wait.parity.acquire.cta.shared::cta.b64 P1, [%0], %1, 0x989680;\n\t@P1 bra.uni WD_%=;\n\tbra.uni WL_%=;\n\tWD_%=:\n\t}" \
            :: "r"(_m), "r"(_p) : "memory"); \
    } } while(0)
#define BULK_G2S(dst, src, bytes, mb) \
    asm volatile("cp.async.bulk.shared::cluster.global.mbarrier::complete_tx::bytes [%0], [%1], %2, [%3];" \
        :: "r"((uint32_t)(dst)), "l"(src), "r"((uint32_t)(bytes)), "r"((uint32_t)(mb)) : "memory")

#define LDMX4(r, a) \
    asm volatile("ldmatrix.sync.aligned.m8n8.x4.shared.b16 {%0,%1,%2,%3}, [%4];" \
        : "=r"((r)[0]), "=r"((r)[1]), "=r"((r)[2]), "=r"((r)[3]) : "r"(a))

__device__ __forceinline__ void mma16816(float* c, const uint32_t* a, uint32_t b0, uint32_t b1){
    asm volatile("mma.sync.aligned.m16n8k16.row.col.f32.f16.f16.f32 "
        "{%0,%1,%2,%3}, {%4,%5,%6,%7}, {%8,%9}, {%0,%1,%2,%3};"
        : "+f"(c[0]), "+f"(c[1]), "+f"(c[2]), "+f"(c[3])
        : "r"(a[0]), "r"(a[1]), "r"(a[2]), "r"(a[3]), "r"(b0), "r"(b1));
}

__device__ __forceinline__ uint32_t tswz(int row, int g){
    return (uint32_t)(row*128 + (((g ^ (row & 7))) << 4));
}

// ---------------------------------------------------------------------------
// 1) Aggregation: LDS.128 gather, 4 nodes per warp (lane groups of 8).
//    Per (quad, g, e): 1 LDS.128 (512B, 4 conflict-free quarter-warp phases)
//    + 4 HADD2. Same crossbar bytes, 1/4 the LDS instructions.
// ---------------------------------------------------------------------------
__global__ __launch_bounds__(1024) void agg_k(const __half* __restrict__ Sh,
        const int* __restrict__ nf, const float* __restrict__ emb,
        const int* __restrict__ nn_idx, const float* __restrict__ mask,
        int D, int nch, int useEmb, int nsplit_shift){
    extern __shared__ __half sbuf[];                // [1024][64]
    int b   = blockIdx.x;
    int d0c = blockIdx.y * 64;
    int tid = threadIdx.x, lane = tid & 31, w = tid >> 5;

    if (useEmb){
        const int* nfb = nf + b*NN;
        for (int i = tid; i < NN*32; i += 1024){
            int row = i >> 5, cp = (i & 31) << 1;
            const float* ep = emb + (size_t)nfb[row]*D0 + d0c + cp;
            float2 v = make_float2(ep[0], ep[1]);
            *(__half2*)&sbuf[row*64 + cp] = __floats2half2_rn(v.x, v.y);
        }
    } else {
        const __half* Sb = Sh + (size_t)b*NN*HH;
        for (int i = tid; i < NN*16; i += 1024){
            int row = i >> 4, cp = (i & 15) << 2;
            *(uint2*)&sbuf[row*64 + cp] = *(const uint2*)&Sb[(size_t)row*HH + d0c + cp];
        }
    }
    __syncthreads();

    int nPer  = NN >> nsplit_shift;
    int nbase = blockIdx.z * nPer;
    char* Ag = (char*)g_Af;
    int p = lane & 7, grp = lane >> 3;              // 16B granule, node group

    for (int n0 = nbase + 4*w; n0 < nbase + nPer; n0 += 128){
        int nj = n0 + grp;                          // this lane's node
        const int4* ip4 = (const int4*)(nn_idx + (size_t)(b*NN + nj)*(KK*EE));
        const __half2* sp = (const __half2*)(sbuf) + p*4;   // granule base (4 half2)

        __half2 acc[4][4];
        #pragma unroll
        for (int e = 0; e < 4; e++)
            #pragma unroll
            for (int i = 0; i < 4; i++) acc[e][i] = __float2half2_rn(0.f);

        #pragma unroll 4
        for (int g = 0; g < KK; g++){
            int4 q = __ldg(&ip4[g]);                // per-group: e=0..3 indices
            const __half2* r0 = sp + q.x*32;
            const __half2* r1 = sp + q.y*32;
            const __half2* r2 = sp + q.z*32;
            const __half2* r3 = sp + q.w*32;
            uint4 v0 = *(const uint4*)r0;
            uint4 v1 = *(const uint4*)r1;
            uint4 v2 = *(const uint4*)r2;
            uint4 v3 = *(const uint4*)r3;
            const __half2* h0 = (const __half2*)&v0;
            const __half2* h1 = (const __half2*)&v1;
            const __half2* h2 = (const __half2*)&v2;
            const __half2* h3 = (const __half2*)&v3;
            #pragma unroll
            for (int i = 0; i < 4; i++){
                acc[0][i] = __hadd2(acc[0][i], h0[i]);
                acc[1][i] = __hadd2(acc[1][i], h1[i]);
                acc[2][i] = __hadd2(acc[2][i], h2[i]);
                acc[3][i] = __hadd2(acc[3][i], h3[i]);
            }
        }

        __half2 m2 = __float2half2_rn(mask[b*NN + nj] * 0.0625f);  // exact pow2
        int mtile = b*8 + (nj >> 7);
        int mrow  = nj & 127;
        size_t tbase = ((size_t)mtile*nch) << 14;
        uint32_t inrow = (((uint32_t)(p ^ (mrow & 7))) << 4);
        #pragma unroll
        for (int e = 0; e < EE; e++){
            __half2 r[4];
            #pragma unroll
            for (int i = 0; i < 4; i++) r[i] = __hmul2(acc[e][i], m2);
            int ch = (e*D + d0c) >> 6;
            *(uint4*)(Ag + tbase + (((size_t)ch*128 + mrow) << 7) + inrow) = *(uint4*)r;
        }
    }
}

// ---------------------------------------------------------------------------
// 2) Weight convert (both layers, one launch)
// ---------------------------------------------------------------------------
__global__ void convw_k(const float* __restrict__ W0, const float* __restrict__ W1){
    int t = blockIdx.x*256 + threadIdx.x;           // 0 .. 49151
    const float* W; __half *Bh, *Bl; int g;
    if (t < 16384){ W = W0; Bh = g_Bh0; Bl = g_Bl0; g = t; }
    else          { W = W1; Bh = g_Bh1; Bl = g_Bl1; g = t - 16384; }
    int n  = g & 255;
    int kq = g >> 8;
    __half hv[8], lv[8];
    #pragma unroll
    for (int j = 0; j < 8; j++){
        float v = W[(size_t)(kq*8 + j)*HH + n];
        __half h = __float2half(v);
        hv[j] = h;
        lv[j] = __float2half(v - __half2float(h));
    }
    int ch = kq >> 3;
    size_t byt = (((size_t)(ch*256 + n)) << 7) + ((((kq & 7) ^ (n & 7))) << 4);
    *(uint4*)((char*)Bh + byt) = *(uint4*)hv;
    *(uint4*)((char*)Bl + byt) = *(uint4*)lv;
}

// ---------------------------------------------------------------------------
// 3) GEMM: 2-pass compensated fp16, cp.async.bulk staging, fused
//    bias+ReLU+L2-norm epilogue; writes fp32 + fp16 state.
// ---------------------------------------------------------------------------
#define STG 81920
#define GEMM_SMEM (2*STG + 64)
#define EPI_STR 258

__global__ __launch_bounds__(512, 1) void gemm2_k(
        const __half* __restrict__ Agl, const __half* __restrict__ Bhg,
        const __half* __restrict__ Blg, int nch,
        const float* __restrict__ bias, float* __restrict__ S){
    extern __shared__ char smx[];
    uint32_t sb0 = smem_u32(smx);
    uint32_t mb  = sb0 + 2*STG;
    int tid = threadIdx.x, lane = tid & 31, w = tid >> 5;
    int wm = w >> 3, wn = w & 7;
    int mtile = blockIdx.x;

    if (tid == 0){ MBAR_INIT(mb, 1); MBAR_INIT(mb + 8, 1); }
    __syncthreads();

    float c[4][4][4];
    #pragma unroll
    for (int mi = 0; mi < 4; mi++)
        #pragma unroll
        for (int nj = 0; nj < 4; nj++)
            #pragma unroll
            for (int q = 0; q < 4; q++) c[mi][nj][q] = 0.f;

    auto issue = [&](int ch){
        int st = ch & 1;
        uint32_t d = sb0 + st*STG;
        uint32_t m = mb + st*8;
        MBAR_EXPECT(m, STG);
        BULK_G2S(d,         (const char*)Agl + (((size_t)(mtile*nch + ch)) << 14), 16384, m);
        BULK_G2S(d + 16384, (const char*)Bhg + (((size_t)ch) << 15),               32768, m);
        BULK_G2S(d + 49152, (const char*)Blg + (((size_t)ch) << 15),               32768, m);
    };

    if (tid == 0){ issue(0); issue(1); }
    int ph0 = 0, ph1 = 0;

    for (int ch = 0; ch < nch; ch++){
        int st = ch & 1;
        if (st == 0){ MBAR_WAIT(mb,     ph0); ph0 ^= 1; }
        else        { MBAR_WAIT(mb + 8, ph1); ph1 ^= 1; }

        uint32_t ab = sb0 + st*STG;
        uint32_t bh = ab + 16384;
        uint32_t bl = ab + 49152;
        #pragma unroll
        for (int s = 0; s < 4; s++){
            int lrow = lane & 15;
            int g = 2*s + (lane >> 4);
            uint32_t a[4][4], bq[2][4], bp[2][4];
            #pragma unroll
            for (int mi = 0; mi < 4; mi++){
                int row = wm*64 + mi*16 + lrow;
                LDMX4(a[mi], ab + tswz(row, g));
            }
            #pragma unroll
            for (int nj = 0; nj < 2; nj++){
                int row = wn*32 + nj*16 + lrow;
                LDMX4(bq[nj], bh + tswz(row, g));
                LDMX4(bp[nj], bl + tswz(row, g));
            }
            #pragma unroll
            for (int mi = 0; mi < 4; mi++)
                #pragma unroll
                for (int nj = 0; nj < 2; nj++){
                    mma16816(c[mi][2*nj+0], a[mi], bq[nj][0], bq[nj][2]);
                    mma16816(c[mi][2*nj+1], a[mi], bq[nj][1], bq[nj][3]);
                    mma16816(c[mi][2*nj+0], a[mi], bp[nj][0], bp[nj][2]);
                    mma16816(c[mi][2*nj+1], a[mi], bp[nj][1], bp[nj][3]);
                }
        }
        __syncthreads();
        if (tid == 0 && ch + 2 < nch) issue(ch + 2);
    }
    __syncthreads();

    // --- epilogue: bias + relu into smem, fused row L2-norm ---
    float* sbuf = (float*)smx;
    int qr = lane >> 2, qc = (lane & 3)*2;
    #pragma unroll
    for (int mi = 0; mi < 4; mi++){
        int r0 = wm*64 + mi*16 + qr;
        #pragma unroll
        for (int nj = 0; nj < 4; nj++){
            int col = wn*32 + nj*8 + qc;
            float b0 = bias[col], b1 = bias[col+1];
            *(float2*)&sbuf[(size_t)r0*EPI_STR + col] =
                make_float2(fmaxf(c[mi][nj][0] + b0, 0.f), fmaxf(c[mi][nj][1] + b1, 0.f));
            *(float2*)&sbuf[(size_t)(r0+8)*EPI_STR + col] =
                make_float2(fmaxf(c[mi][nj][2] + b0, 0.f), fmaxf(c[mi][nj][3] + b1, 0.f));
        }
    }
    __syncthreads();

    int m0 = mtile*128;
    #pragma unroll
    for (int r = 0; r < 8; r++){
        int row = w*8 + r;
        const float2* rp2 = (const float2*)&sbuf[(size_t)row*EPI_STR];
        float2 v2[4]; float ss = 0.f;
        #pragma unroll
        for (int j = 0; j < 4; j++){
            v2[j] = rp2[lane + 32*j];
            ss += v2[j].x*v2[j].x + v2[j].y*v2[j].y;
        }
        #pragma unroll
        for (int off = 16; off; off >>= 1) ss += __shfl_xor_sync(0xffffffffu, ss, off);
        float inv = 1.0f/(sqrtf(ss) + EPSF);
        float2*  op  = (float2*)(S + (size_t)(m0 + row)*HH);
        __half2* oph = (__half2*)(g_stateh + (size_t)(m0 + row)*HH);
        #pragma unroll
        for (int j = 0; j < 4; j++){
            float x = v2[j].x*inv, y = v2[j].y*inv;
            op[lane + 32*j]  = make_float2(x, y);
            oph[lane + 32*j] = __floats2half2_rn(x, y);
        }
    }
}

// ---------------------------------------------------------------------------
// 4) Output head + pooling
// ---------------------------------------------------------------------------
__global__ void final_k(const float* __restrict__ S,
                        const float* __restrict__ Wout, const float* __restrict__ bout,
                        const float* __restrict__ Watt, const float* __restrict__ batt){
    __shared__ float wt[PP*HH];
    __shared__ float wa[HH];
    __shared__ float red[8][PP];
    int b = blockIdx.x, seg = blockIdx.y;
    int tid = threadIdx.x, lane = tid & 31, w = tid >> 5;

    for (int i = tid; i < PP*HH; i += 256){
        int d = i / PP, p = i - d*PP;
        wt[p*HH + d] = Wout[i];
    }
    if (tid < HH) wa[tid] = Watt[tid];
    __syncthreads();

    float accp = 0.f;
    float ba = batt[0];
    for (int t = 0; t < 16; t++){
        int n = seg*128 + w*16 + t;
        const float* sp = S + (size_t)(b*NN + n)*HH;
        float s[8], att = 0.f, y[PP];
        #pragma unroll
        for (int p = 0; p < PP; p++) y[p] = 0.f;
        #pragma unroll
        for (int j = 0; j < 8; j++){
            s[j] = sp[lane + 32*j];
            att += s[j]*wa[lane + 32*j];
        }
        #pragma unroll
        for (int p = 0; p < PP; p++)
            #pragma unroll
            for (int j = 0; j < 8; j++) y[p] += s[j]*wt[p*HH + lane + 32*j];
        #pragma unroll
        for (int off = 16; off; off >>= 1){
            att += __shfl_xor_sync(0xffffffffu, att, off);
            #pragma unroll
            for (int p = 0; p < PP; p++) y[p] += __shfl_xor_sync(0xffffffffu, y[p], off);
        }
        float a = 1.0f/(1.0f + expf(-(att + ba)));
        if (lane < PP) accp += a * (y[lane] + bout[lane]);
    }
    if (lane < PP) red[w][lane] = accp;
    __syncthreads();
    if (tid < PP){
        float sum = 0.f;
        #pragma unroll
        for (int w2 = 0; w2 < 8; w2++) sum += red[w2][tid];
        g_pool[(b*8 + seg)*PP + tid] = sum;
    }
}

__global__ void reduce_k(float* __restrict__ out){
    int i = threadIdx.x;
    if (i < BB*PP){
        int b = i / PP, p = i - b*PP;
        float s = 0.f;
        #pragma unroll
        for (int seg = 0; seg < 8; seg++) s += g_pool[(b*8 + seg)*PP + p];
        out[i] = s * (1.0f/NN);
    }
}

// ---------------------------------------------------------------------------
extern "C" void kernel_launch(void* const* d_in, const int* in_sizes, int n_in,
                              void* d_out, int out_size){
    (void)in_sizes; (void)n_in; (void)out_size;
    const int*   nf   = (const int*)  d_in[0];
    const int*   nn   = (const int*)  d_in[1];
    const float* mask = (const float*)d_in[2];
    const float* emb  = (const float*)d_in[3];
    const float* W0   = (const float*)d_in[4];
    const float* b0   = (const float*)d_in[5];
    const float* W1   = (const float*)d_in[6];
    const float* b1   = (const float*)d_in[7];
    const float* Wout = (const float*)d_in[8];
    const float* bout = (const float*)d_in[9];
    const float* Watt = (const float*)d_in[10];
    const float* batt = (const float*)d_in[11];
    float* out = (float*)d_out;

    float *state; __half *stateh, *af, *bh0, *bl0, *bh1, *bl1;
    cudaGetSymbolAddress((void**)&state,  g_state);
    cudaGetSymbolAddress((void**)&stateh, g_stateh);
    cudaGetSymbolAddress((void**)&af,  g_Af);
    cudaGetSymbolAddress((void**)&bh0, g_Bh0);
    cudaGetSymbolAddress((void**)&bl0, g_Bl0);
    cudaGetSymbolAddress((void**)&bh1, g_Bh1);
    cudaGetSymbolAddress((void**)&bl1, g_Bl1);

    cudaFuncSetAttribute(agg_k,   cudaFuncAttributeMaxDynamicSharedMemorySize, 131072);
    cudaFuncSetAttribute(gemm2_k, cudaFuncAttributeMaxDynamicSharedMemorySize, GEMM_SMEM);

    convw_k<<<192, 256>>>(W0, W1);

    // Layer 0 (Kd=512, nch=8): embed fused, 64-col slices, z-split 4, 32 warps
    agg_k<<<dim3(BB, D0/64, 4), 1024, 131072>>>(stateh, nf, emb, nn, mask, D0, 8, 1, 2);
    gemm2_k<<<MTILES, 512, GEMM_SMEM>>>(af, bh0, bl0, 8, b0, state);

    // Layer 1 (Kd=1024, nch=16): fp16 state fill, z-split 2, 32 warps
    agg_k<<<dim3(BB, HH/64, 2), 1024, 131072>>>(stateh, nf, emb, nn, mask, HH, 16, 0, 1);
    gemm2_k<<<MTILES, 512, GEMM_SMEM>>>(af, bh1, bl1, 16, b1, state);

    final_k<<<dim3(BB, 8), 256>>>(state, Wout, bout, Watt, batt);
    reduce_k<<<1, 192>>>(out);
}

// round 10
// speedup vs baseline: 2.0993x; 1.1102x over previous
#include <cuda_runtime.h>
#include <cuda_fp16.h>
#include <math.h>
#include <stdint.h>

#define BB 16
#define NN 1024
#define KK 16
#define EE 4
#define D0 128
#define HH 256
#define PP 10
#define EPSF 1.1920928955078125e-07f

#define NCH1 16
#define MTILES 128         // BB*NN/128

// ---------------- device scratch (allocation-free rule) --------------------
__device__ __half g_Af[MTILES*NCH1*128*64];       // A tiled fp16, swizzled
__device__ __half g_Bh0[8*256*64];
__device__ __half g_Bl0[8*256*64];
__device__ __half g_Bh1[16*256*64];
__device__ __half g_Bl1[16*256*64];
__device__ __half g_stateh[BB*NN*HH];             // fp16 states (agg fill)
__device__ float  g_pool[MTILES*PP];

// ---------------- PTX helpers ----------------------------------------------
__device__ __forceinline__ uint32_t smem_u32(const void* p){
    uint32_t a; asm("{ .reg .u64 t; cvta.to.shared.u64 t, %1; cvt.u32.u64 %0, t; }" : "=r"(a) : "l"(p));
    return a;
}
#define MBAR_INIT(mb, c)  asm volatile("mbarrier.init.shared.b64 [%0], %1;" :: "r"((uint32_t)(mb)), "r"((uint32_t)(c)) : "memory")
#define MBAR_EXPECT(mb, tx) asm volatile("mbarrier.arrive.expect_tx.shared.b64 _, [%0], %1;" :: "r"((uint32_t)(mb)), "r"((uint32_t)(tx)) : "memory")
#define MBAR_WAIT(mb, ph) do { \
    uint32_t _m = (uint32_t)(mb), _p = (uint32_t)(ph), _d; \
    asm volatile("{\n\t.reg .pred p;\n\tmbarrier.try_wait.parity.acquire.cta.shared::cta.b64 p, [%1], %2;\n\tselp.b32 %0, 1, 0, p;\n\t}" \
        : "=r"(_d) : "r"(_m), "r"(_p) : "memory"); \
    if (!_d) { \
        asm volatile("{\n\t.reg .pred P1;\n\tWL_%=:\n\tmbarrier.try_wait.parity.acquire.cta.shared::cta.b64 P1, [%0], %1, 0x989680;\n\t@P1 bra.uni WD_%=;\n\tbra.uni WL_%=;\n\tWD_%=:\n\t}" \
            :: "r"(_m), "r"(_p) : "memory"); \
    } } while(0)
#define BULK_G2S(dst, src, bytes, mb) \
    asm volatile("cp.async.bulk.shared::cluster.global.mbarrier::complete_tx::bytes [%0], [%1], %2, [%3];" \
        :: "r"((uint32_t)(dst)), "l"(src), "r"((uint32_t)(bytes)), "r"((uint32_t)(mb)) : "memory")

#define LDMX4(r, a) \
    asm volatile("ldmatrix.sync.aligned.m8n8.x4.shared.b16 {%0,%1,%2,%3}, [%4];" \
        : "=r"((r)[0]), "=r"((r)[1]), "=r"((r)[2]), "=r"((r)[3]) : "r"(a))

__device__ __forceinline__ void mma16816(float* c, const uint32_t* a, uint32_t b0, uint32_t b1){
    asm volatile("mma.sync.aligned.m16n8k16.row.col.f32.f16.f16.f32 "
        "{%0,%1,%2,%3}, {%4,%5,%6,%7}, {%8,%9}, {%0,%1,%2,%3};"
        : "+f"(c[0]), "+f"(c[1]), "+f"(c[2]), "+f"(c[3])
        : "r"(a[0]), "r"(a[1]), "r"(a[2]), "r"(a[3]), "r"(b0), "r"(b1));
}

__device__ __forceinline__ uint32_t tswz(int row, int g){
    return (uint32_t)(row*128 + (((g ^ (row & 7))) << 4));
}

// ---------------------------------------------------------------------------
// 1) Aggregation: LDS.128 gather (4 nodes/warp), indices staged in SMEM
//    per 256-node phase (no LDG latency in hot loop).
//    SMEM: half[1024][64] slice (128KB) + int4[256][16] indices (64KB).
// ---------------------------------------------------------------------------
#define AGG_SMEM 196608
__global__ __launch_bounds__(1024) void agg_k(const __half* __restrict__ Sh,
        const int* __restrict__ nf, const float* __restrict__ emb,
        const int* __restrict__ nn_idx, const float* __restrict__ mask,
        int D, int nch, int useEmb, int nsplit_shift){
    extern __shared__ char smraw[];
    __half* sbuf = (__half*)smraw;                  // [1024][64]
    int4*   sidx = (int4*)(smraw + 131072);         // [256][16]
    int b   = blockIdx.x;
    int d0c = blockIdx.y * 64;
    int tid = threadIdx.x, lane = tid & 31, w = tid >> 5;

    if (useEmb){
        const int* nfb = nf + b*NN;
        for (int i = tid; i < NN*32; i += 1024){
            int row = i >> 5, cp = (i & 31) << 1;
            const float* ep = emb + (size_t)nfb[row]*D0 + d0c + cp;
            float2 v = make_float2(ep[0], ep[1]);
            *(__half2*)&sbuf[row*64 + cp] = __floats2half2_rn(v.x, v.y);
        }
    } else {
        const __half* Sb = Sh + (size_t)b*NN*HH;
        for (int i = tid; i < NN*16; i += 1024){
            int row = i >> 4, cp = (i & 15) << 2;
            *(uint2*)&sbuf[row*64 + cp] = *(const uint2*)&Sb[(size_t)row*HH + d0c + cp];
        }
    }

    int nPer  = NN >> nsplit_shift;
    int nbase = blockIdx.z * nPer;
    char* Ag = (char*)g_Af;
    int p = lane & 7, grp = lane >> 3;              // 16B granule, node group
    int nph = nPer >> 8;

    for (int ph = 0; ph < nph; ph++){
        int pb = nbase + (ph << 8);
        const int4* gi = (const int4*)nn_idx + (size_t)(b*NN + pb)*16;
        __syncthreads();                            // fill done / prev phase done
        #pragma unroll
        for (int i = 0; i < 4; i++) sidx[tid + i*1024] = gi[tid + i*1024];
        __syncthreads();

        #pragma unroll
        for (int n0 = 0; n0 < 256; n0 += 128){
            int nl = 4*w + n0 + grp;                // node local to phase
            int nj = pb + nl;
            const __half2* sp = (const __half2*)sbuf + p*4;

            __half2 acc[4][4];
            #pragma unroll
            for (int e = 0; e < 4; e++)
                #pragma unroll
                for (int i = 0; i < 4; i++) acc[e][i] = __float2half2_rn(0.f);

            #pragma unroll 4
            for (int g = 0; g < KK; g++){
                int4 q = sidx[nl*16 + g];           // broadcast LDS
                uint4 v0 = *(const uint4*)(sp + q.x*32);
                uint4 v1 = *(const uint4*)(sp + q.y*32);
                uint4 v2 = *(const uint4*)(sp + q.z*32);
                uint4 v3 = *(const uint4*)(sp + q.w*32);
                const __half2* h0 = (const __half2*)&v0;
                const __half2* h1 = (const __half2*)&v1;
                const __half2* h2 = (const __half2*)&v2;
                const __half2* h3 = (const __half2*)&v3;
                #pragma unroll
                for (int i = 0; i < 4; i++){
                    acc[0][i] = __hadd2(acc[0][i], h0[i]);
                    acc[1][i] = __hadd2(acc[1][i], h1[i]);
                    acc[2][i] = __hadd2(acc[2][i], h2[i]);
                    acc[3][i] = __hadd2(acc[3][i], h3[i]);
                }
            }

            __half2 m2 = __float2half2_rn(mask[b*NN + nj] * 0.0625f);  // exact pow2
            int mtile = b*8 + (nj >> 7);
            int mrow  = nj & 127;
            size_t tbase = ((size_t)mtile*nch) << 14;
            uint32_t inrow = (((uint32_t)(p ^ (mrow & 7))) << 4);
            #pragma unroll
            for (int e = 0; e < EE; e++){
                __half2 r[4];
                #pragma unroll
                for (int i = 0; i < 4; i++) r[i] = __hmul2(acc[e][i], m2);
                int ch = (e*D + d0c) >> 6;
                *(uint4*)(Ag + tbase + (((size_t)ch*128 + mrow) << 7) + inrow) = *(uint4*)r;
            }
        }
    }
}

// ---------------------------------------------------------------------------
// 2) Weight convert (both layers, one launch)
// ---------------------------------------------------------------------------
__global__ void convw_k(const float* __restrict__ W0, const float* __restrict__ W1){
    int t = blockIdx.x*256 + threadIdx.x;           // 0 .. 49151
    const float* W; __half *Bh, *Bl; int g;
    if (t < 16384){ W = W0; Bh = g_Bh0; Bl = g_Bl0; g = t; }
    else          { W = W1; Bh = g_Bh1; Bl = g_Bl1; g = t - 16384; }
    int n  = g & 255;
    int kq = g >> 8;
    __half hv[8], lv[8];
    #pragma unroll
    for (int j = 0; j < 8; j++){
        float v = W[(size_t)(kq*8 + j)*HH + n];
        __half h = __float2half(v);
        hv[j] = h;
        lv[j] = __float2half(v - __half2float(h));
    }
    int ch = kq >> 3;
    size_t byt = (((size_t)(ch*256 + n)) << 7) + ((((kq & 7) ^ (n & 7))) << 4);
    *(uint4*)((char*)Bh + byt) = *(uint4*)hv;
    *(uint4*)((char*)Bl + byt) = *(uint4*)lv;
}

// ---------------------------------------------------------------------------
// 3) GEMM: 2-pass compensated fp16 + fused bias/ReLU/L2-norm epilogue.
//    fuse=0: write fp16 state.  fuse=1: fused output head —
//    score partial = (sum_n a_n*s_n)@Wout + (sum_n a_n)*bout  per CTA.
// ---------------------------------------------------------------------------
#define STG 81920
#define GEMM_SMEM (2*STG + 64)
#define EPI_STR 258
// epilogue smem offsets (bytes), after sbuf = 128*258*4 = 132096
#define OFF_WA   132096
#define OFF_WT   133120      // [256][12] floats = 12288
#define OFF_ZRED 145408      // [16][264] floats = 16896
#define OFF_ARED 162304      // [16] floats
#define OFF_ZFIN 162368      // [256] floats -> ends 163392 (< mbar @163840)

__global__ __launch_bounds__(512, 1) void gemm2_k(
        const __half* __restrict__ Agl, const __half* __restrict__ Bhg,
        const __half* __restrict__ Blg, int nch,
        const float* __restrict__ bias, __half* __restrict__ Sout,
        int fuse, const float* __restrict__ Wout, const float* __restrict__ bout,
        const float* __restrict__ Watt, const float* __restrict__ batt){
    extern __shared__ char smx[];
    uint32_t sb0 = smem_u32(smx);
    uint32_t mb  = sb0 + 2*STG;
    int tid = threadIdx.x, lane = tid & 31, w = tid >> 5;
    int wm = w >> 3, wn = w & 7;
    int mtile = blockIdx.x;

    if (tid == 0){ MBAR_INIT(mb, 1); MBAR_INIT(mb + 8, 1); }
    __syncthreads();

    float c[4][4][4];
    #pragma unroll
    for (int mi = 0; mi < 4; mi++)
        #pragma unroll
        for (int nj = 0; nj < 4; nj++)
            #pragma unroll
            for (int q = 0; q < 4; q++) c[mi][nj][q] = 0.f;

    auto issue = [&](int ch){
        int st = ch & 1;
        uint32_t d = sb0 + st*STG;
        uint32_t m = mb + st*8;
        MBAR_EXPECT(m, STG);
        BULK_G2S(d,         (const char*)Agl + (((size_t)(mtile*nch + ch)) << 14), 16384, m);
        BULK_G2S(d + 16384, (const char*)Bhg + (((size_t)ch) << 15),               32768, m);
        BULK_G2S(d + 49152, (const char*)Blg + (((size_t)ch) << 15),               32768, m);
    };

    if (tid == 0){ issue(0); issue(1); }
    int ph0 = 0, ph1 = 0;

    for (int ch = 0; ch < nch; ch++){
        int st = ch & 1;
        if (st == 0){ MBAR_WAIT(mb,     ph0); ph0 ^= 1; }
        else        { MBAR_WAIT(mb + 8, ph1); ph1 ^= 1; }

        uint32_t ab = sb0 + st*STG;
        uint32_t bh = ab + 16384;
        uint32_t bl = ab + 49152;
        #pragma unroll
        for (int s = 0; s < 4; s++){
            int lrow = lane & 15;
            int g = 2*s + (lane >> 4);
            uint32_t a[4][4], bq[2][4], bp[2][4];
            #pragma unroll
            for (int mi = 0; mi < 4; mi++){
                int row = wm*64 + mi*16 + lrow;
                LDMX4(a[mi], ab + tswz(row, g));
            }
            #pragma unroll
            for (int nj = 0; nj < 2; nj++){
                int row = wn*32 + nj*16 + lrow;
                LDMX4(bq[nj], bh + tswz(row, g));
                LDMX4(bp[nj], bl + tswz(row, g));
            }
            #pragma unroll
            for (int mi = 0; mi < 4; mi++)
                #pragma unroll
                for (int nj = 0; nj < 2; nj++){
                    mma16816(c[mi][2*nj+0], a[mi], bq[nj][0], bq[nj][2]);
                    mma16816(c[mi][2*nj+1], a[mi], bq[nj][1], bq[nj][3]);
                    mma16816(c[mi][2*nj+0], a[mi], bp[nj][0], bp[nj][2]);
                    mma16816(c[mi][2*nj+1], a[mi], bp[nj][1], bp[nj][3]);
                }
        }
        __syncthreads();
        if (tid == 0 && ch + 2 < nch) issue(ch + 2);
    }
    __syncthreads();

    // --- Phase A: bias + relu into sbuf; head weights into smem (fuse) ---
    float* sbuf = (float*)smx;
    int qr = lane >> 2, qc = (lane & 3)*2;
    #pragma unroll
    for (int mi = 0; mi < 4; mi++){
        int r0 = wm*64 + mi*16 + qr;
        #pragma unroll
        for (int nj = 0; nj < 4; nj++){
            int col = wn*32 + nj*8 + qc;
            float b0 = bias[col], b1 = bias[col+1];
            *(float2*)&sbuf[(size_t)r0*EPI_STR + col] =
                make_float2(fmaxf(c[mi][nj][0] + b0, 0.f), fmaxf(c[mi][nj][1] + b1, 0.f));
            *(float2*)&sbuf[(size_t)(r0+8)*EPI_STR + col] =
                make_float2(fmaxf(c[mi][nj][2] + b0, 0.f), fmaxf(c[mi][nj][3] + b1, 0.f));
        }
    }
    float* wa = (float*)(smx + OFF_WA);
    float* wt = (float*)(smx + OFF_WT);
    if (fuse){
        for (int i = tid; i < 256; i += 512) wa[i] = Watt[i];
        for (int i = tid; i < 256*PP; i += 512){
            int d = i / PP, p2 = i - d*PP;
            wt[d*12 + p2] = Wout[i];
        }
    }
    __syncthreads();

    // --- Phase B ---
    int m0 = mtile*128;
    if (!fuse){
        #pragma unroll
        for (int r = 0; r < 8; r++){
            int row = w*8 + r;
            const float2* rp2 = (const float2*)&sbuf[(size_t)row*EPI_STR];
            float2 v2[4]; float ss = 0.f;
            #pragma unroll
            for (int j = 0; j < 4; j++){
                v2[j] = rp2[lane + 32*j];
                ss += v2[j].x*v2[j].x + v2[j].y*v2[j].y;
            }
            #pragma unroll
            for (int off = 16; off; off >>= 1) ss += __shfl_xor_sync(0xffffffffu, ss, off);
            float inv = 1.0f/(sqrtf(ss) + EPSF);
            __half2* oph = (__half2*)(Sout + (size_t)(m0 + row)*HH);
            #pragma unroll
            for (int j = 0; j < 4; j++)
                oph[lane + 32*j] = __floats2half2_rn(v2[j].x*inv, v2[j].y*inv);
        }
    } else {
        float* zred = (float*)(smx + OFF_ZRED);
        float* ared = (float*)(smx + OFF_ARED);
        float* zfin = (float*)(smx + OFF_ZFIN);
        float ba = batt[0];
        float2 zacc[4];
        #pragma unroll
        for (int j = 0; j < 4; j++) zacc[j] = make_float2(0.f, 0.f);
        float Aacc = 0.f;
        #pragma unroll
        for (int r = 0; r < 8; r++){
            int row = w*8 + r;
            const float2* rp2 = (const float2*)&sbuf[(size_t)row*EPI_STR];
            float2 v2[4]; float ss = 0.f;
            #pragma unroll
            for (int j = 0; j < 4; j++){
                v2[j] = rp2[lane + 32*j];
                ss += v2[j].x*v2[j].x + v2[j].y*v2[j].y;
            }
            #pragma unroll
            for (int off = 16; off; off >>= 1) ss += __shfl_xor_sync(0xffffffffu, ss, off);
            float inv = 1.0f/(sqrtf(ss) + EPSF);
            float att = 0.f;
            #pragma unroll
            for (int j = 0; j < 4; j++){
                int c0 = 2*lane + 64*j;
                att += v2[j].x*inv*wa[c0] + v2[j].y*inv*wa[c0+1];
            }
            #pragma unroll
            for (int off = 16; off; off >>= 1) att += __shfl_xor_sync(0xffffffffu, att, off);
            float a = 1.0f/(1.0f + expf(-(att + ba)));
            float ai = a * inv;
            #pragma unroll
            for (int j = 0; j < 4; j++){
                zacc[j].x += ai * v2[j].x;
                zacc[j].y += ai * v2[j].y;
            }
            Aacc += a;
        }
        #pragma unroll
        for (int j = 0; j < 4; j++)
            *(float2*)&zred[w*264 + 2*lane + 64*j] = zacc[j];
        if (lane == 0) ared[w] = Aacc;
        __syncthreads();
        if (tid < 256){
            float s = 0.f;
            #pragma unroll
            for (int w2 = 0; w2 < 16; w2++) s += zred[w2*264 + tid];
            zfin[tid] = s;
        }
        __syncthreads();
        if (tid < PP){
            float A = 0.f;
            #pragma unroll
            for (int w2 = 0; w2 < 16; w2++) A += ared[w2];
            float sc = A * bout[tid];
            for (int d = 0; d < 256; d++) sc += zfin[d] * wt[d*12 + tid];
            g_pool[mtile*PP + tid] = sc;
        }
    }
}

// ---------------------------------------------------------------------------
// 4) Final reduce: out[b][p] = (1/N) * sum over 8 tile-partials
// ---------------------------------------------------------------------------
__global__ void reduce_k(float* __restrict__ out){
    int i = threadIdx.x;
    if (i < BB*PP){
        int b = i / PP, p = i - b*PP;
        float s = 0.f;
        #pragma unroll
        for (int seg = 0; seg < 8; seg++) s += g_pool[(b*8 + seg)*PP + p];
        out[i] = s * (1.0f/NN);
    }
}

// ---------------------------------------------------------------------------
extern "C" void kernel_launch(void* const* d_in, const int* in_sizes, int n_in,
                              void* d_out, int out_size){
    (void)in_sizes; (void)n_in; (void)out_size;
    const int*   nf   = (const int*)  d_in[0];
    const int*   nn   = (const int*)  d_in[1];
    const float* mask = (const float*)d_in[2];
    const float* emb  = (const float*)d_in[3];
    const float* W0   = (const float*)d_in[4];
    const float* b0   = (const float*)d_in[5];
    const float* W1   = (const float*)d_in[6];
    const float* b1   = (const float*)d_in[7];
    const float* Wout = (const float*)d_in[8];
    const float* bout = (const float*)d_in[9];
    const float* Watt = (const float*)d_in[10];
    const float* batt = (const float*)d_in[11];
    float* out = (float*)d_out;

    __half *stateh, *af, *bh0, *bl0, *bh1, *bl1;
    cudaGetSymbolAddress((void**)&stateh, g_stateh);
    cudaGetSymbolAddress((void**)&af,  g_Af);
    cudaGetSymbolAddress((void**)&bh0, g_Bh0);
    cudaGetSymbolAddress((void**)&bl0, g_Bl0);
    cudaGetSymbolAddress((void**)&bh1, g_Bh1);
    cudaGetSymbolAddress((void**)&bl1, g_Bl1);

    cudaFuncSetAttribute(agg_k,   cudaFuncAttributeMaxDynamicSharedMemorySize, AGG_SMEM);
    cudaFuncSetAttribute(gemm2_k, cudaFuncAttributeMaxDynamicSharedMemorySize, GEMM_SMEM);

    convw_k<<<192, 256>>>(W0, W1);

    // Layer 0 (Kd=512, nch=8): embed fused, 64-col slices, z-split 4 (1 phase)
    agg_k<<<dim3(BB, D0/64, 4), 1024, AGG_SMEM>>>(stateh, nf, emb, nn, mask, D0, 8, 1, 2);
    gemm2_k<<<MTILES, 512, GEMM_SMEM>>>(af, bh0, bl0, 8, b0, stateh,
                                        0, nullptr, nullptr, nullptr, nullptr);

    // Layer 1 (Kd=1024, nch=16): z-split 2 (2 phases); fused output head
    agg_k<<<dim3(BB, HH/64, 2), 1024, AGG_SMEM>>>(stateh, nf, emb, nn, mask, HH, 16, 0, 1);
    gemm2_k<<<MTILES, 512, GEMM_SMEM>>>(af, bh1, bl1, 16, b1, stateh,
                                        1, Wout, bout, Watt, batt);

    reduce_k<<<1, 192>>>(out);
}

// round 12
// speedup vs baseline: 2.2060x; 1.0508x over previous
#include <cuda_runtime.h>
#include <cuda_fp16.h>
#include <math.h>
#include <stdint.h>

#define BB 16
#define NN 1024
#define KK 16
#define EE 4
#define D0 128
#define HH 256
#define PP 10
#define EPSF 1.1920928955078125e-07f

#define NCH1 16
#define MTILES 128         // BB*NN/128

// ---------------- device scratch (allocation-free rule) --------------------
__device__ __half g_Af[MTILES*NCH1*128*64];       // A tiled fp16, swizzled
__device__ __half g_Bh0[8*256*64];
__device__ __half g_Bl0[8*256*64];
__device__ __half g_Bh1[16*256*64];
__device__ __half g_Bl1[16*256*64];
__device__ __half g_stateh[BB*NN*HH];             // fp16 states (agg fill)
__device__ float  g_pool[MTILES*PP];

// ---------------- PTX helpers ----------------------------------------------
__device__ __forceinline__ uint32_t smem_u32(const void* p){
    uint32_t a; asm("{ .reg .u64 t; cvta.to.shared.u64 t, %1; cvt.u32.u64 %0, t; }" : "=r"(a) : "l"(p));
    return a;
}
#define MBAR_INIT(mb, c)  asm volatile("mbarrier.init.shared.b64 [%0], %1;" :: "r"((uint32_t)(mb)), "r"((uint32_t)(c)) : "memory")
#define MBAR_EXPECT(mb, tx) asm volatile("mbarrier.arrive.expect_tx.shared.b64 _, [%0], %1;" :: "r"((uint32_t)(mb)), "r"((uint32_t)(tx)) : "memory")
#define MBAR_WAIT(mb, ph) do { \
    uint32_t _m = (uint32_t)(mb), _p = (uint32_t)(ph), _d; \
    asm volatile("{\n\t.reg .pred p;\n\tmbarrier.try_wait.parity.acquire.cta.shared::cta.b64 p, [%1], %2;\n\tselp.b32 %0, 1, 0, p;\n\t}" \
        : "=r"(_d) : "r"(_m), "r"(_p) : "memory"); \
    if (!_d) { \
        asm volatile("{\n\t.reg .pred P1;\n\tWL_%=:\n\tmbarrier.try_wait.parity.acquire.cta.shared::cta.b64 P1, [%0], %1, 0x989680;\n\t@P1 bra.uni WD_%=;\n\tbra.uni WL_%=;\n\tWD_%=:\n\t}" \
            :: "r"(_m), "r"(_p) : "memory"); \
    } } while(0)
#define BULK_G2S(dst, src, bytes, mb) \
    asm volatile("cp.async.bulk.shared::cluster.global.mbarrier::complete_tx::bytes [%0], [%1], %2, [%3];" \
        :: "r"((uint32_t)(dst)), "l"(src), "r"((uint32_t)(bytes)), "r"((uint32_t)(mb)) : "memory")

#define LDMX4(r, a) \
    asm volatile("ldmatrix.sync.aligned.m8n8.x4.shared.b16 {%0,%1,%2,%3}, [%4];" \
        : "=r"((r)[0]), "=r"((r)[1]), "=r"((r)[2]), "=r"((r)[3]) : "r"(a))

__device__ __forceinline__ void mma16816(float* c, const uint32_t* a, uint32_t b0, uint32_t b1){
    asm volatile("mma.sync.aligned.m16n8k16.row.col.f32.f16.f16.f32 "
        "{%0,%1,%2,%3}, {%4,%5,%6,%7}, {%8,%9}, {%0,%1,%2,%3};"
        : "+f"(c[0]), "+f"(c[1]), "+f"(c[2]), "+f"(c[3])
        : "r"(a[0]), "r"(a[1]), "r"(a[2]), "r"(a[3]), "r"(b0), "r"(b1));
}

__device__ __forceinline__ uint32_t tswz(int row, int g){
    return (uint32_t)(row*128 + (((g ^ (row & 7))) << 4));
}

// ---------------------------------------------------------------------------
// 1) Aggregation: LDS.128 gather (4 nodes/warp), direct __ldg(int4) indices
//    (R8-proven: SMEM index staging costs more crossbar than it saves).
//    Extra blocks (blockIdx.z == zconv) convert weights for BOTH layers,
//    overlapping the conversion with layer-0 aggregation on idle SMs.
// ---------------------------------------------------------------------------
#define AGG_SMEM 131072
__global__ __launch_bounds__(1024) void agg_k(const __half* __restrict__ Sh,
        const int* __restrict__ nf, const float* __restrict__ emb,
        const int* __restrict__ nn_idx, const float* __restrict__ mask,
        const float* __restrict__ W0, const float* __restrict__ W1,
        int D, int nch, int useEmb, int nsplit_shift, int zconv){
    extern __shared__ char smraw[];
    __half* sbuf = (__half*)smraw;                  // [1024][64]
    int tid = threadIdx.x, lane = tid & 31, w = tid >> 5;

    // ---- weight-conversion blocks (overlapped with layer-0 agg) ----
    if ((int)blockIdx.z == zconv){
        int bid = blockIdx.x * gridDim.y + blockIdx.y;   // 0..31
        for (int t = bid*1024 + tid; t < 49152; t += 32*1024){
            const float* W; __half *Bh, *Bl; int g;
            if (t < 16384){ W = W0; Bh = g_Bh0; Bl = g_Bl0; g = t; }
            else          { W = W1; Bh = g_Bh1; Bl = g_Bl1; g = t - 16384; }
            int n  = g & 255;
            int kq = g >> 8;
            __half hv[8], lv[8];
            #pragma unroll
            for (int j = 0; j < 8; j++){
                float v = W[(size_t)(kq*8 + j)*HH + n];
                __half h = __float2half(v);
                hv[j] = h;
                lv[j] = __float2half(v - __half2float(h));
            }
            int ch = kq >> 3;
            size_t byt = (((size_t)(ch*256 + n)) << 7) + ((((kq & 7) ^ (n & 7))) << 4);
            *(uint4*)((char*)Bh + byt) = *(uint4*)hv;
            *(uint4*)((char*)Bl + byt) = *(uint4*)lv;
        }
        return;
    }

    int b   = blockIdx.x;
    int d0c = blockIdx.y * 64;

    if (useEmb){
        const int* nfb = nf + b*NN;
        for (int i = tid; i < NN*32; i += 1024){
            int row = i >> 5, cp = (i & 31) << 1;
            const float* ep = emb + (size_t)nfb[row]*D0 + d0c + cp;
            float2 v = make_float2(ep[0], ep[1]);
            *(__half2*)&sbuf[row*64 + cp] = __floats2half2_rn(v.x, v.y);
        }
    } else {
        const __half* Sb = Sh + (size_t)b*NN*HH;
        for (int i = tid; i < NN*16; i += 1024){
            int row = i >> 4, cp = (i & 15) << 2;
            *(uint2*)&sbuf[row*64 + cp] = *(const uint2*)&Sb[(size_t)row*HH + d0c + cp];
        }
    }
    __syncthreads();

    int nPer  = NN >> nsplit_shift;
    int nbase = blockIdx.z * nPer;
    char* Ag = (char*)g_Af;
    int p = lane & 7, grp = lane >> 3;              // 16B granule, node group

    for (int n0 = nbase + 4*w; n0 < nbase + nPer; n0 += 128){
        int nj = n0 + grp;                          // this lane's node
        const int4* ip4 = (const int4*)(nn_idx + (size_t)(b*NN + nj)*(KK*EE));
        const __half2* sp = (const __half2*)sbuf + p*4;

        __half2 acc[4][4];
        #pragma unroll
        for (int e = 0; e < 4; e++)
            #pragma unroll
            for (int i = 0; i < 4; i++) acc[e][i] = __float2half2_rn(0.f);

        #pragma unroll 4
        for (int g = 0; g < KK; g++){
            int4 q = __ldg(&ip4[g]);                // per-group: e=0..3 indices
            uint4 v0 = *(const uint4*)(sp + q.x*32);
            uint4 v1 = *(const uint4*)(sp + q.y*32);
            uint4 v2 = *(const uint4*)(sp + q.z*32);
            uint4 v3 = *(const uint4*)(sp + q.w*32);
            const __half2* h0 = (const __half2*)&v0;
            const __half2* h1 = (const __half2*)&v1;
            const __half2* h2 = (const __half2*)&v2;
            const __half2* h3 = (const __half2*)&v3;
            #pragma unroll
            for (int i = 0; i < 4; i++){
                acc[0][i] = __hadd2(acc[0][i], h0[i]);
                acc[1][i] = __hadd2(acc[1][i], h1[i]);
                acc[2][i] = __hadd2(acc[2][i], h2[i]);
                acc[3][i] = __hadd2(acc[3][i], h3[i]);
            }
        }

        __half2 m2 = __float2half2_rn(mask[b*NN + nj] * 0.0625f);  // exact pow2
        int mtile = b*8 + (nj >> 7);
        int mrow  = nj & 127;
        size_t tbase = ((size_t)mtile*nch) << 14;
        uint32_t inrow = (((uint32_t)(p ^ (mrow & 7))) << 4);
        #pragma unroll
        for (int e = 0; e < EE; e++){
            __half2 r[4];
            #pragma unroll
            for (int i = 0; i < 4; i++) r[i] = __hmul2(acc[e][i], m2);
            int ch = (e*D + d0c) >> 6;
            *(uint4*)(Ag + tbase + (((size_t)ch*128 + mrow) << 7) + inrow) = *(uint4*)r;
        }
    }
}

// ---------------------------------------------------------------------------
// 2) GEMM: 2-pass compensated fp16 + fused bias/ReLU/L2-norm epilogue.
//    fuse=0: write fp16 state.  fuse=1: fused output head —
//    score partial = (sum_n a_n*s_n)@Wout + (sum_n a_n)*bout  per CTA.
// ---------------------------------------------------------------------------
#define STG 81920
#define GEMM_SMEM (2*STG + 64)
#define EPI_STR 258
// epilogue smem offsets (bytes), after sbuf = 128*258*4 = 132096
#define OFF_WA   132096
#define OFF_WT   133120      // [256][12] floats = 12288
#define OFF_ZRED 145408      // [16][264] floats = 16896
#define OFF_ARED 162304      // [16] floats
#define OFF_ZFIN 162368      // [256] floats -> ends 163392 (< mbar @163840)

__global__ __launch_bounds__(512, 1) void gemm2_k(
        const __half* __restrict__ Agl, const __half* __restrict__ Bhg,
        const __half* __restrict__ Blg, int nch,
        const float* __restrict__ bias, __half* __restrict__ Sout,
        int fuse, const float* __restrict__ Wout, const float* __restrict__ bout,
        const float* __restrict__ Watt, const float* __restrict__ batt){
    extern __shared__ char smx[];
    uint32_t sb0 = smem_u32(smx);
    uint32_t mb  = sb0 + 2*STG;
    int tid = threadIdx.x, lane = tid & 31, w = tid >> 5;
    int wm = w >> 3, wn = w & 7;
    int mtile = blockIdx.x;

    if (tid == 0){ MBAR_INIT(mb, 1); MBAR_INIT(mb + 8, 1); }
    __syncthreads();

    float c[4][4][4];
    #pragma unroll
    for (int mi = 0; mi < 4; mi++)
        #pragma unroll
        for (int nj = 0; nj < 4; nj++)
            #pragma unroll
            for (int q = 0; q < 4; q++) c[mi][nj][q] = 0.f;

    auto issue = [&](int ch){
        int st = ch & 1;
        uint32_t d = sb0 + st*STG;
        uint32_t m = mb + st*8;
        MBAR_EXPECT(m, STG);
        BULK_G2S(d,         (const char*)Agl + (((size_t)(mtile*nch + ch)) << 14), 16384, m);
        BULK_G2S(d + 16384, (const char*)Bhg + (((size_t)ch) << 15),               32768, m);
        BULK_G2S(d + 49152, (const char*)Blg + (((size_t)ch) << 15),               32768, m);
    };

    if (tid == 0){ issue(0); issue(1); }
    int ph0 = 0, ph1 = 0;

    for (int ch = 0; ch < nch; ch++){
        int st = ch & 1;
        if (st == 0){ MBAR_WAIT(mb,     ph0); ph0 ^= 1; }
        else        { MBAR_WAIT(mb + 8, ph1); ph1 ^= 1; }

        uint32_t ab = sb0 + st*STG;
        uint32_t bh = ab + 16384;
        uint32_t bl = ab + 49152;
        #pragma unroll
        for (int s = 0; s < 4; s++){
            int lrow = lane & 15;
            int g = 2*s + (lane >> 4);
            uint32_t a[4][4], bq[2][4], bp[2][4];
            #pragma unroll
            for (int mi = 0; mi < 4; mi++){
                int row = wm*64 + mi*16 + lrow;
                LDMX4(a[mi], ab + tswz(row, g));
            }
            #pragma unroll
            for (int nj = 0; nj < 2; nj++){
                int row = wn*32 + nj*16 + lrow;
                LDMX4(bq[nj], bh + tswz(row, g));
                LDMX4(bp[nj], bl + tswz(row, g));
            }
            #pragma unroll
            for (int mi = 0; mi < 4; mi++)
                #pragma unroll
                for (int nj = 0; nj < 2; nj++){
                    mma16816(c[mi][2*nj+0], a[mi], bq[nj][0], bq[nj][2]);
                    mma16816(c[mi][2*nj+1], a[mi], bq[nj][1], bq[nj][3]);
                    mma16816(c[mi][2*nj+0], a[mi], bp[nj][0], bp[nj][2]);
                    mma16816(c[mi][2*nj+1], a[mi], bp[nj][1], bp[nj][3]);
                }
        }
        __syncthreads();
        if (tid == 0 && ch + 2 < nch) issue(ch + 2);
    }
    __syncthreads();

    // --- Phase A: bias + relu into sbuf; head weights into smem (fuse) ---
    float* sbuf = (float*)smx;
    int qr = lane >> 2, qc = (lane & 3)*2;
    #pragma unroll
    for (int mi = 0; mi < 4; mi++){
        int r0 = wm*64 + mi*16 + qr;
        #pragma unroll
        for (int nj = 0; nj < 4; nj++){
            int col = wn*32 + nj*8 + qc;
            float b0 = bias[col], b1 = bias[col+1];
            *(float2*)&sbuf[(size_t)r0*EPI_STR + col] =
                make_float2(fmaxf(c[mi][nj][0] + b0, 0.f), fmaxf(c[mi][nj][1] + b1, 0.f));
            *(float2*)&sbuf[(size_t)(r0+8)*EPI_STR + col] =
                make_float2(fmaxf(c[mi][nj][2] + b0, 0.f), fmaxf(c[mi][nj][3] + b1, 0.f));
        }
    }
    float* wa = (float*)(smx + OFF_WA);
    float* wt = (float*)(smx + OFF_WT);
    if (fuse){
        for (int i = tid; i < 256; i += 512) wa[i] = Watt[i];
        for (int i = tid; i < 256*PP; i += 512){
            int d = i / PP, p2 = i - d*PP;
            wt[d*12 + p2] = Wout[i];
        }
    }
    __syncthreads();

    // --- Phase B ---
    int m0 = mtile*128;
    if (!fuse){
        #pragma unroll
        for (int r = 0; r < 8; r++){
            int row = w*8 + r;
            const float2* rp2 = (const float2*)&sbuf[(size_t)row*EPI_STR];
            float2 v2[4]; float ss = 0.f;
            #pragma unroll
            for (int j = 0; j < 4; j++){
                v2[j] = rp2[lane + 32*j];
                ss += v2[j].x*v2[j].x + v2[j].y*v2[j].y;
            }
            #pragma unroll
            for (int off = 16; off; off >>= 1) ss += __shfl_xor_sync(0xffffffffu, ss, off);
            float inv = 1.0f/(sqrtf(ss) + EPSF);
            __half2* oph = (__half2*)(Sout + (size_t)(m0 + row)*HH);
            #pragma unroll
            for (int j = 0; j < 4; j++)
                oph[lane + 32*j] = __floats2half2_rn(v2[j].x*inv, v2[j].y*inv);
        }
    } else {
        float* zred = (float*)(smx + OFF_ZRED);
        float* ared = (float*)(smx + OFF_ARED);
        float* zfin = (float*)(smx + OFF_ZFIN);
        float ba = batt[0];
        float2 zacc[4];
        #pragma unroll
        for (int j = 0; j < 4; j++) zacc[j] = make_float2(0.f, 0.f);
        float Aacc = 0.f;
        #pragma unroll
        for (int r = 0; r < 8; r++){
            int row = w*8 + r;
            const float2* rp2 = (const float2*)&sbuf[(size_t)row*EPI_STR];
            float2 v2[4]; float ss = 0.f;
            #pragma unroll
            for (int j = 0; j < 4; j++){
                v2[j] = rp2[lane + 32*j];
                ss += v2[j].x*v2[j].x + v2[j].y*v2[j].y;
            }
            #pragma unroll
            for (int off = 16; off; off >>= 1) ss += __shfl_xor_sync(0xffffffffu, ss, off);
            float inv = 1.0f/(sqrtf(ss) + EPSF);
            float att = 0.f;
            #pragma unroll
            for (int j = 0; j < 4; j++){
                int c0 = 2*lane + 64*j;
                att += v2[j].x*inv*wa[c0] + v2[j].y*inv*wa[c0+1];
            }
            #pragma unroll
            for (int off = 16; off; off >>= 1) att += __shfl_xor_sync(0xffffffffu, att, off);
            float a = 1.0f/(1.0f + expf(-(att + ba)));
            float ai = a * inv;
            #pragma unroll
            for (int j = 0; j < 4; j++){
                zacc[j].x += ai * v2[j].x;
                zacc[j].y += ai * v2[j].y;
            }
            Aacc += a;
        }
        #pragma unroll
        for (int j = 0; j < 4; j++)
            *(float2*)&zred[w*264 + 2*lane + 64*j] = zacc[j];
        if (lane == 0) ared[w] = Aacc;
        __syncthreads();
        if (tid < 256){
            float s = 0.f;
            #pragma unroll
            for (int w2 = 0; w2 < 16; w2++) s += zred[w2*264 + tid];
            zfin[tid] = s;
        }
        __syncthreads();
        if (tid < PP){
            float A = 0.f;
            #pragma unroll
            for (int w2 = 0; w2 < 16; w2++) A += ared[w2];
            float sc = A * bout[tid];
            for (int d = 0; d < 256; d++) sc += zfin[d] * wt[d*12 + tid];
            g_pool[mtile*PP + tid] = sc;
        }
    }
}

// ---------------------------------------------------------------------------
// 3) Final reduce: out[b][p] = (1/N) * sum over 8 tile-partials
// ---------------------------------------------------------------------------
__global__ void reduce_k(float* __restrict__ out){
    int i = threadIdx.x;
    if (i < BB*PP){
        int b = i / PP, p = i - b*PP;
        float s = 0.f;
        #pragma unroll
        for (int seg = 0; seg < 8; seg++) s += g_pool[(b*8 + seg)*PP + p];
        out[i] = s * (1.0f/NN);
    }
}

// ---------------------------------------------------------------------------
extern "C" void kernel_launch(void* const* d_in, const int* in_sizes, int n_in,
                              void* d_out, int out_size){
    (void)in_sizes; (void)n_in; (void)out_size;
    const int*   nf   = (const int*)  d_in[0];
    const int*   nn   = (const int*)  d_in[1];
    const float* mask = (const float*)d_in[2];
    const float* emb  = (const float*)d_in[3];
    const float* W0   = (const float*)d_in[4];
    const float* b0   = (const float*)d_in[5];
    const float* W1   = (const float*)d_in[6];
    const float* b1   = (const float*)d_in[7];
    const float* Wout = (const float*)d_in[8];
    const float* bout = (const float*)d_in[9];
    const float* Watt = (const float*)d_in[10];
    const float* batt = (const float*)d_in[11];
    float* out = (float*)d_out;

    __half *stateh, *af, *bh0, *bl0, *bh1, *bl1;
    cudaGetSymbolAddress((void**)&stateh, g_stateh);
    cudaGetSymbolAddress((void**)&af,  g_Af);
    cudaGetSymbolAddress((void**)&bh0, g_Bh0);
    cudaGetSymbolAddress((void**)&bl0, g_Bl0);
    cudaGetSymbolAddress((void**)&bh1, g_Bh1);
    cudaGetSymbolAddress((void**)&bl1, g_Bl1);

    cudaFuncSetAttribute(agg_k,   cudaFuncAttributeMaxDynamicSharedMemorySize, AGG_SMEM);
    cudaFuncSetAttribute(gemm2_k, cudaFuncAttributeMaxDynamicSharedMemorySize, GEMM_SMEM);

    // Layer 0 (Kd=512, nch=8): embed fused, z-split 4; z==4 blocks convert
    // weights for BOTH layers on otherwise-idle SMs.
    agg_k<<<dim3(BB, D0/64, 5), 1024, AGG_SMEM>>>(stateh, nf, emb, nn, mask,
                                                  W0, W1, D0, 8, 1, 2, 4);
    gemm2_k<<<MTILES, 512, GEMM_SMEM>>>(af, bh0, bl0, 8, b0, stateh,
                                        0, nullptr, nullptr, nullptr, nullptr);

    // Layer 1 (Kd=1024, nch=16): z-split 2; fused output head
    agg_k<<<dim3(BB, HH/64, 2), 1024, AGG_SMEM>>>(stateh, nf, emb, nn, mask,
                                                  W0, W1, HH, 16, 0, 1, -1);
    gemm2_k<<<MTILES, 512, GEMM_SMEM>>>(af, bh1, bl1, 16, b1, stateh,
                                        1, Wout, bout, Watt, batt);

    reduce_k<<<1, 192>>>(out);
}